// round 8
// baseline (speedup 1.0000x reference)
#include <cuda_runtime.h>
#include <cuda_fp16.h>
#include <cstdint>
#include <math.h>

#define BATCH   4096
#define IN_DIM  1024
#define OUT_DIM 1024
#define NK      96
#define RANK    192
#define SCALE_F 0.03125f                    // 1/32 exactly
#define G_SCALE 1024.0f                     // keeps Glo in fp16 normal range
#define SCALE_EPI (SCALE_F / G_SCALE)

typedef __half h16;

// ---------------- scratch (device globals) ----------------------------------
__device__ h16 g_Fhi[RANK * IN_DIM];     // [192][1024] K-major
__device__ h16 g_Flo[RANK * IN_DIM];
__device__ h16 g_Ghi[OUT_DIM * RANK];    // [1024][192] K-major, scaled by 1024
__device__ h16 g_Glo[OUT_DIM * RANK];
__device__ h16 g_Th [BATCH * RANK];

// ---------------- helpers ----------------------------------------------------
__device__ __forceinline__ uint32_t smem_u32(const void* p) {
    uint32_t a;
    asm("{ .reg .u64 t; cvta.to.shared.u64 t, %1; cvt.u32.u64 %0, t; }" : "=r"(a) : "l"(p));
    return a;
}
__device__ __forceinline__ void cp_async16(uint32_t s, const void* g) {
    asm volatile("cp.async.cg.shared.global [%0], [%1], 16;\n" :: "r"(s), "l"(g));
}
__device__ __forceinline__ void cp_commit() {
    asm volatile("cp.async.commit_group;\n" ::: "memory");
}
template <int N>
__device__ __forceinline__ void cp_wait() {
    asm volatile("cp.async.wait_group %0;\n" :: "n"(N) : "memory");
}
__device__ __forceinline__ void ldm_x4(uint32_t& r0, uint32_t& r1, uint32_t& r2, uint32_t& r3,
                                       uint32_t addr) {
    asm volatile("ldmatrix.sync.aligned.m8n8.x4.shared.b16 {%0,%1,%2,%3}, [%4];"
                 : "=r"(r0), "=r"(r1), "=r"(r2), "=r"(r3) : "r"(addr));
}
__device__ __forceinline__ void mma_fp16(float* c, const uint32_t* a, uint32_t b0, uint32_t b1) {
    asm volatile(
        "mma.sync.aligned.m16n8k16.row.col.f32.f16.f16.f32 "
        "{%0,%1,%2,%3}, {%4,%5,%6,%7}, {%8,%9}, {%0,%1,%2,%3};"
        : "+f"(c[0]), "+f"(c[1]), "+f"(c[2]), "+f"(c[3])
        : "r"(a[0]), "r"(a[1]), "r"(a[2]), "r"(a[3]), "r"(b0), "r"(b1));
}
__device__ __forceinline__ uint32_t h2u(__half2 h) { return *reinterpret_cast<uint32_t*>(&h); }

// ---------------------------------------------------------------------------
// prep: factor build only.
//   blocks [0,192)  F factors (i-contiguous, coalesced half2 stores)
//   blocks [192,384) G factors (k-contiguous, coalesced half2 stores)
// ---------------------------------------------------------------------------
__global__ void prep_kernel(const float* __restrict__ omega,
                            const float* __restrict__ phi,
                            const float* __restrict__ alpha) {
    int b = blockIdx.x;
    if (b < 192) {
        int idx = b * 256 + threadIdx.x;
        int i2 = (idx & 511) << 1;
        int k  = idx >> 9;
        float w0 = omega[3 * k + 0];
        float s0, c0, s1, c1;
        sincosf(w0 * ((float)(i2 + 1) / 1025.0f), &s0, &c0);
        sincosf(w0 * ((float)(i2 + 2) / 1025.0f), &s1, &c1);
        h16 sh0 = __float2half_rn(s0), sh1 = __float2half_rn(s1);
        h16 ch0 = __float2half_rn(c0), ch1 = __float2half_rn(c1);
        __half2* Fhi2 = reinterpret_cast<__half2*>(g_Fhi);
        __half2* Flo2 = reinterpret_cast<__half2*>(g_Flo);
        int o_s = (k * 1024 + i2) >> 1;
        int o_c = ((NK + k) * 1024 + i2) >> 1;
        Fhi2[o_s] = __halves2half2(sh0, sh1);
        Fhi2[o_c] = __halves2half2(ch0, ch1);
        Flo2[o_s] = __halves2half2(__float2half_rn(s0 - __half2float(sh0)),
                                   __float2half_rn(s1 - __half2float(sh1)));
        Flo2[o_c] = __halves2half2(__float2half_rn(c0 - __half2float(ch0)),
                                   __float2half_rn(c1 - __half2float(ch1)));
        return;
    }
    int idx = (b - 192) * 256 + threadIdx.x;
    int kp = idx % 48;
    int j  = idx / 48;
    int k2 = kp << 1;
    float p = (float)(j + 1) / 1025.0f;

    float gs[2], gc[2];
#pragma unroll
    for (int q = 0; q < 2; q++) {
        int k = k2 + q;
        float w1 = omega[3 * k + 1], w2 = omega[3 * k + 2];
        float Bv = fmaf(w1, p, fmaf(w2, 0.5f, phi[k]));
        float sb, cb;
        sincosf(Bv, &sb, &cb);
        float as = alpha[k], ac = alpha[NK + k];
        gs[q] = (as * cb - ac * sb) * G_SCALE;
        gc[q] = (as * sb + ac * cb) * G_SCALE;
    }
    h16 gsh0 = __float2half_rn(gs[0]), gsh1 = __float2half_rn(gs[1]);
    h16 gch0 = __float2half_rn(gc[0]), gch1 = __float2half_rn(gc[1]);
    __half2* Ghi2 = reinterpret_cast<__half2*>(g_Ghi);
    __half2* Glo2 = reinterpret_cast<__half2*>(g_Glo);
    int o_s = (j * RANK + k2) >> 1;
    int o_c = (j * RANK + NK + k2) >> 1;
    Ghi2[o_s] = __halves2half2(gsh0, gsh1);
    Ghi2[o_c] = __halves2half2(gch0, gch1);
    Glo2[o_s] = __halves2half2(__float2half_rn(gs[0] - __half2float(gsh0)),
                               __float2half_rn(gs[1] - __half2float(gsh1)));
    Glo2[o_c] = __halves2half2(__float2half_rn(gc[0] - __half2float(gch0)),
                               __float2half_rn(gc[1] - __half2float(gch1)));
}

// ---------------------------------------------------------------------------
// GEMM1 (fused convert): Th = fp16( x @ F^T ),
//   x fp32 [4096][1024] staged raw in smem; A fragments built via LDS+cvt.
//   C = A @ Fhi^T + A @ Flo^T  (fp32 accum).
// BM=64, BN=64, 128 threads (2x2 warps), 5-stage ring.
// ---------------------------------------------------------------------------
__global__ __launch_bounds__(128, 2) void gemm1_kernel(
    const float* __restrict__ X,
    const h16* __restrict__ Bhi, const h16* __restrict__ Blo,
    h16* __restrict__ Ch) {
    constexpr int KA = IN_DIM;
    constexpr int STRA = 36;                 // fp32 words per A smem row (32+4 pad)
    constexpr int STR = 40;                  // halves per B smem row
    constexpr int A_BYTES = 64 * STRA * 4;   // 9216
    constexpr int SS = A_BYTES + 128 * STR * 2;  // 19456 per stage
    constexpr int STAGES = 5, NC = 32;

    extern __shared__ char smem[];
    const uint32_t su = smem_u32(smem);
    float* sf = reinterpret_cast<float*>(smem);

    const int t = threadIdx.x, w = t >> 5, lane = t & 31;
    const int wm = w & 1, wn = w >> 1;
    const int m0 = blockIdx.y * 64, n0 = blockIdx.x * 64;

    auto issue = [&](int c, int buf) {
        const int k0 = c * 32;
        const uint32_t sbase = su + buf * SS;
        // A: 64 rows x 32 fp32, 8 threads/row x 16B
#pragma unroll
        for (int i = 0; i < 4; i++) {
            int idx = t + i * 128;
            int r = idx >> 3, c4 = (idx & 7) * 4;
            cp_async16(sbase + (r * STRA + c4) * 4, X + (size_t)(m0 + r) * KA + k0 + c4);
        }
        // B: 64 rows Bhi + 64 rows Blo, fp16, 4 threads/row x 16B
#pragma unroll
        for (int i = 0; i < 4; i++) {
            int idx = t + i * 128;
            int r = idx >> 2, c8 = (idx & 3) * 8;
            const h16* g = (r < 64) ? (Bhi + (size_t)(n0 + r) * KA + k0 + c8)
                                    : (Blo + (size_t)(n0 + r - 64) * KA + k0 + c8);
            cp_async16(sbase + A_BYTES + (r * STR + c8) * 2, g);
        }
        cp_commit();
    };

    float acc[2][4][4];
#pragma unroll
    for (int mi = 0; mi < 2; mi++)
#pragma unroll
        for (int ni = 0; ni < 4; ni++)
#pragma unroll
            for (int q = 0; q < 4; q++) acc[mi][ni][q] = 0.0f;

    auto compute = [&](int buf) {
        const uint32_t sbB = su + buf * SS + A_BYTES;
        const int fbase = buf * (SS / 4);
        uint32_t aF[2][2][4], bH[2][2][4], bL[2][2][4];
        const int r = lane >> 2, cp = (lane & 3) * 2;
#pragma unroll
        for (int kk = 0; kk < 2; kk++)
#pragma unroll
            for (int mi = 0; mi < 2; mi++) {
                int row0 = wm * 32 + mi * 16;
                int off = fbase + (row0 + r) * STRA + kk * 16 + cp;
                float2 f0 = *reinterpret_cast<const float2*>(sf + off);
                float2 f1 = *reinterpret_cast<const float2*>(sf + off + 8 * STRA);
                float2 f2 = *reinterpret_cast<const float2*>(sf + off + 8);
                float2 f3 = *reinterpret_cast<const float2*>(sf + off + 8 * STRA + 8);
                aF[kk][mi][0] = h2u(__floats2half2_rn(f0.x, f0.y));
                aF[kk][mi][1] = h2u(__floats2half2_rn(f1.x, f1.y));
                aF[kk][mi][2] = h2u(__floats2half2_rn(f2.x, f2.y));
                aF[kk][mi][3] = h2u(__floats2half2_rn(f3.x, f3.y));
            }
#pragma unroll
        for (int kk = 0; kk < 2; kk++)
#pragma unroll
            for (int nj = 0; nj < 2; nj++) {
                uint32_t addr = sbB +
                    ((wn * 32 + nj * 16 + (lane & 15)) * STR + kk * 16 + (lane >> 4) * 8) * 2;
                ldm_x4(bH[kk][nj][0], bH[kk][nj][1], bH[kk][nj][2], bH[kk][nj][3], addr);
                ldm_x4(bL[kk][nj][0], bL[kk][nj][1], bL[kk][nj][2], bL[kk][nj][3],
                       addr + 64 * STR * 2);
            }
#pragma unroll
        for (int kk = 0; kk < 2; kk++)
#pragma unroll
            for (int mi = 0; mi < 2; mi++)
#pragma unroll
                for (int nj = 0; nj < 2; nj++) {
                    mma_fp16(acc[mi][2 * nj],     aF[kk][mi], bH[kk][nj][0], bH[kk][nj][2]);
                    mma_fp16(acc[mi][2 * nj + 1], aF[kk][mi], bH[kk][nj][1], bH[kk][nj][3]);
                    mma_fp16(acc[mi][2 * nj],     aF[kk][mi], bL[kk][nj][0], bL[kk][nj][2]);
                    mma_fp16(acc[mi][2 * nj + 1], aF[kk][mi], bL[kk][nj][1], bL[kk][nj][3]);
                }
    };

#pragma unroll 1
    for (int s = 0; s < STAGES - 1; s++) issue(s, s);
#pragma unroll 1
    for (int c = 0; c < NC; c++) {
        cp_wait<STAGES - 2>();
        __syncthreads();
        if (c + STAGES - 1 < NC) issue(c + STAGES - 1, (c + STAGES - 1) % STAGES);
        else cp_commit();
        compute(c % STAGES);
    }

#pragma unroll
    for (int mi = 0; mi < 2; mi++) {
        int r0 = m0 + wm * 32 + mi * 16 + (lane >> 2);
#pragma unroll
        for (int ni = 0; ni < 4; ni++) {
            int cc = n0 + wn * 32 + ni * 8 + (lane & 3) * 2;
            *reinterpret_cast<__half2*>(Ch + (size_t)r0 * RANK + cc) =
                __floats2half2_rn(acc[mi][ni][0], acc[mi][ni][1]);
            *reinterpret_cast<__half2*>(Ch + (size_t)(r0 + 8) * RANK + cc) =
                __floats2half2_rn(acc[mi][ni][2], acc[mi][ni][3]);
        }
    }
}

// ---------------------------------------------------------------------------
// GEMM2: out = SCALE_EPI*(Th @ G'^T) + bias.  fp16 A, B-side hi/lo split.
// BM=128, BN=64, 256 threads (4x2 warps), 4-stage ring.
// ---------------------------------------------------------------------------
__global__ __launch_bounds__(256, 2) void gemm2_kernel(
    const h16* __restrict__ A,
    const h16* __restrict__ Bhi, const h16* __restrict__ Blo,
    float* __restrict__ Cf, const float* __restrict__ bias) {
    constexpr int KA = RANK;
    constexpr int STR = 40;
    constexpr int ROWS = 128 + 2 * 64;
    constexpr int SS = ROWS * STR;           // halves per stage
    constexpr int STAGES = 4, NC = 6;

    extern __shared__ char smem_raw[];
    h16* smem = reinterpret_cast<h16*>(smem_raw);
    const uint32_t su = smem_u32(smem);

    const int t = threadIdx.x, w = t >> 5, lane = t & 31;
    const int wm = w & 3, wn = w >> 2;
    const int m0 = blockIdx.y * 128, n0 = blockIdx.x * 64;

    auto issue = [&](int c, int buf) {
        const int k0 = c * 32;
        const uint32_t sbase = su + buf * SS * 2;
#pragma unroll
        for (int i = 0; i < 4; i++) {
            int idx = t + i * 256;
            int r = idx >> 2, c8 = (idx & 3) * 8;
            const h16* g;
            uint32_t soff;
            if (r < 128)      { g = A   + (size_t)(m0 + r) * KA + k0 + c8;        soff = r * STR + c8; }
            else if (r < 192) { int rr = r - 128; g = Bhi + (size_t)(n0 + rr) * KA + k0 + c8; soff = (128 + rr) * STR + c8; }
            else              { int rr = r - 192; g = Blo + (size_t)(n0 + rr) * KA + k0 + c8; soff = (192 + rr) * STR + c8; }
            cp_async16(sbase + soff * 2, g);
        }
        cp_commit();
    };

    float acc[2][4][4];
#pragma unroll
    for (int mi = 0; mi < 2; mi++)
#pragma unroll
        for (int ni = 0; ni < 4; ni++)
#pragma unroll
            for (int q = 0; q < 4; q++) acc[mi][ni][q] = 0.0f;

    auto compute = [&](int buf) {
        const uint32_t sbase = su + buf * SS * 2;
        uint32_t aF[2][2][4], bH[2][2][4], bL[2][2][4];
#pragma unroll
        for (int kk = 0; kk < 2; kk++)
#pragma unroll
            for (int mi = 0; mi < 2; mi++) {
                uint32_t addr = sbase +
                    ((wm * 32 + mi * 16 + (lane & 15)) * STR + kk * 16 + (lane >> 4) * 8) * 2;
                ldm_x4(aF[kk][mi][0], aF[kk][mi][1], aF[kk][mi][2], aF[kk][mi][3], addr);
            }
#pragma unroll
        for (int kk = 0; kk < 2; kk++)
#pragma unroll
            for (int nj = 0; nj < 2; nj++) {
                uint32_t addr = sbase + (128 * STR) * 2 +
                    ((wn * 32 + nj * 16 + (lane & 15)) * STR + kk * 16 + (lane >> 4) * 8) * 2;
                ldm_x4(bH[kk][nj][0], bH[kk][nj][1], bH[kk][nj][2], bH[kk][nj][3], addr);
                ldm_x4(bL[kk][nj][0], bL[kk][nj][1], bL[kk][nj][2], bL[kk][nj][3],
                       addr + 64 * STR * 2);
            }
#pragma unroll
        for (int kk = 0; kk < 2; kk++)
#pragma unroll
            for (int mi = 0; mi < 2; mi++)
#pragma unroll
                for (int nj = 0; nj < 2; nj++) {
                    mma_fp16(acc[mi][2 * nj],     aF[kk][mi], bH[kk][nj][0], bH[kk][nj][2]);
                    mma_fp16(acc[mi][2 * nj + 1], aF[kk][mi], bH[kk][nj][1], bH[kk][nj][3]);
                    mma_fp16(acc[mi][2 * nj],     aF[kk][mi], bL[kk][nj][0], bL[kk][nj][2]);
                    mma_fp16(acc[mi][2 * nj + 1], aF[kk][mi], bL[kk][nj][1], bL[kk][nj][3]);
                }
    };

#pragma unroll 1
    for (int s = 0; s < STAGES - 1; s++) issue(s, s);
#pragma unroll 1
    for (int c = 0; c < NC; c++) {
        cp_wait<STAGES - 2>();
        __syncthreads();
        if (c + STAGES - 1 < NC) issue(c + STAGES - 1, (c + STAGES - 1) % STAGES);
        else cp_commit();
        compute(c % STAGES);
    }

#pragma unroll
    for (int mi = 0; mi < 2; mi++) {
        int r0 = m0 + wm * 32 + mi * 16 + (lane >> 2);
#pragma unroll
        for (int ni = 0; ni < 4; ni++) {
            int cc = n0 + wn * 32 + ni * 8 + (lane & 3) * 2;
            float b0 = bias[cc], b1 = bias[cc + 1];
            float2 o0 = {acc[mi][ni][0] * SCALE_EPI + b0, acc[mi][ni][1] * SCALE_EPI + b1};
            float2 o1 = {acc[mi][ni][2] * SCALE_EPI + b0, acc[mi][ni][3] * SCALE_EPI + b1};
            *reinterpret_cast<float2*>(Cf + (size_t)r0 * OUT_DIM + cc) = o0;
            *reinterpret_cast<float2*>(Cf + (size_t)(r0 + 8) * OUT_DIM + cc) = o1;
        }
    }
}

// ---------------------------------------------------------------------------
extern "C" void kernel_launch(void* const* d_in, const int* in_sizes, int n_in,
                              void* d_out, int out_size) {
    const float* x     = (const float*)d_in[0];
    const float* omega = (const float*)d_in[1];
    const float* phi   = (const float*)d_in[2];
    const float* alpha = (const float*)d_in[3];
    const float* bias  = (const float*)d_in[4];
    float* out = (float*)d_out;

    h16 *Fhi, *Flo, *Ghi, *Glo, *Th;
    cudaGetSymbolAddress((void**)&Fhi, g_Fhi);
    cudaGetSymbolAddress((void**)&Flo, g_Flo);
    cudaGetSymbolAddress((void**)&Ghi, g_Ghi);
    cudaGetSymbolAddress((void**)&Glo, g_Glo);
    cudaGetSymbolAddress((void**)&Th,  g_Th);

    const int SMEM1 = 5 * (64 * 36 * 4 + 128 * 40 * 2);   // 97280
    const int SMEM2 = 4 * (128 + 2 * 64) * 40 * 2;        // 81920
    cudaFuncSetAttribute((const void*)gemm1_kernel,
                         cudaFuncAttributeMaxDynamicSharedMemorySize, SMEM1);
    cudaFuncSetAttribute((const void*)gemm2_kernel,
                         cudaFuncAttributeMaxDynamicSharedMemorySize, SMEM2);

    // prep: factor build only (F: [0,192), G: [192,384))
    prep_kernel<<<384, 256>>>(omega, phi, alpha);

    // GEMM1: Th = fp16(x @ F^T)   (M=4096, N=192, K=1024), grid 3 x 64 = 192 CTAs
    gemm1_kernel<<<dim3(RANK / 64, BATCH / 64), 128, SMEM1>>>(x, Fhi, Flo, Th);

    // GEMM2: out = SCALE_EPI*(Th @ G'^T) + bias  (M=4096, N=1024, K=192), grid 16 x 32
    gemm2_kernel<<<dim3(OUT_DIM / 64, BATCH / 128), 256, SMEM2>>>(Th, Ghi, Glo, out, bias);
}

// round 9
// speedup vs baseline: 1.5446x; 1.5446x over previous
#include <cuda_runtime.h>
#include <cuda_fp16.h>
#include <cstdint>
#include <math.h>

#define BATCH   4096
#define IN_DIM  1024
#define OUT_DIM 1024
#define NK      96
#define RANK    192
#define SCALE_F 0.03125f                    // 1/32 exactly
#define G_SCALE 1024.0f                     // keeps Glo in fp16 normal range
#define SCALE_EPI (SCALE_F / G_SCALE)

typedef __half h16;

// ---------------- scratch (device globals) ----------------------------------
__device__ h16 g_xh [BATCH * IN_DIM];
__device__ h16 g_Fhi[RANK * IN_DIM];     // [192][1024] K-major
__device__ h16 g_Flo[RANK * IN_DIM];
__device__ h16 g_Ghi[OUT_DIM * RANK];    // [1024][192] K-major, scaled by 1024
__device__ h16 g_Glo[OUT_DIM * RANK];
__device__ h16 g_Th [BATCH * RANK];

// ---------------- helpers ----------------------------------------------------
__device__ __forceinline__ uint32_t smem_u32(const void* p) {
    uint32_t a;
    asm("{ .reg .u64 t; cvta.to.shared.u64 t, %1; cvt.u32.u64 %0, t; }" : "=r"(a) : "l"(p));
    return a;
}
__device__ __forceinline__ void cp_async16(uint32_t s, const void* g) {
    asm volatile("cp.async.cg.shared.global [%0], [%1], 16;\n" :: "r"(s), "l"(g));
}
__device__ __forceinline__ void cp_commit() {
    asm volatile("cp.async.commit_group;\n" ::: "memory");
}
template <int N>
__device__ __forceinline__ void cp_wait() {
    asm volatile("cp.async.wait_group %0;\n" :: "n"(N) : "memory");
}
__device__ __forceinline__ void ldm_x4(uint32_t& r0, uint32_t& r1, uint32_t& r2, uint32_t& r3,
                                       uint32_t addr) {
    asm volatile("ldmatrix.sync.aligned.m8n8.x4.shared.b16 {%0,%1,%2,%3}, [%4];"
                 : "=r"(r0), "=r"(r1), "=r"(r2), "=r"(r3) : "r"(addr));
}
__device__ __forceinline__ void mma_fp16(float* c, const uint32_t* a, uint32_t b0, uint32_t b1) {
    asm volatile(
        "mma.sync.aligned.m16n8k16.row.col.f32.f16.f16.f32 "
        "{%0,%1,%2,%3}, {%4,%5,%6,%7}, {%8,%9}, {%0,%1,%2,%3};"
        : "+f"(c[0]), "+f"(c[1]), "+f"(c[2]), "+f"(c[3])
        : "r"(a[0]), "r"(a[1]), "r"(a[2]), "r"(a[3]), "r"(b0), "r"(b1));
}
__device__ __forceinline__ uint32_t h2u(__half2 h) { return *reinterpret_cast<uint32_t*>(&h); }

// ---------------------------------------------------------------------------
// prep: blocks [0,512) x->fp16 (MLP=8, 16B stores)
//       blocks [512,704) F factors (i-contiguous, coalesced half2 stores)
//       blocks [704,896) G factors (k-contiguous, coalesced half2 stores)
// ---------------------------------------------------------------------------
__global__ void prep_kernel(const float4* __restrict__ x,
                            const float* __restrict__ omega,
                            const float* __restrict__ phi,
                            const float* __restrict__ alpha) {
    int b = blockIdx.x;
    if (b < 512) {
        int tid = b * 256 + threadIdx.x;
        uint4* dst = reinterpret_cast<uint4*>(g_xh);
        float4 v[8];
#pragma unroll
        for (int p = 0; p < 4; p++) {
            int base = 2 * (tid + p * 131072);
            v[2 * p]     = x[base];
            v[2 * p + 1] = x[base + 1];
        }
#pragma unroll
        for (int p = 0; p < 4; p++) {
            float4 a = v[2 * p], c = v[2 * p + 1];
            uint4 o;
            o.x = h2u(__floats2half2_rn(a.x, a.y));
            o.y = h2u(__floats2half2_rn(a.z, a.w));
            o.z = h2u(__floats2half2_rn(c.x, c.y));
            o.w = h2u(__floats2half2_rn(c.z, c.w));
            dst[tid + p * 131072] = o;
        }
        return;
    }
    if (b < 704) {
        int idx = (b - 512) * 256 + threadIdx.x;
        int i2 = (idx & 511) << 1;
        int k  = idx >> 9;
        float w0 = omega[3 * k + 0];
        float s0, c0, s1, c1;
        sincosf(w0 * ((float)(i2 + 1) / 1025.0f), &s0, &c0);
        sincosf(w0 * ((float)(i2 + 2) / 1025.0f), &s1, &c1);
        h16 sh0 = __float2half_rn(s0), sh1 = __float2half_rn(s1);
        h16 ch0 = __float2half_rn(c0), ch1 = __float2half_rn(c1);
        __half2* Fhi2 = reinterpret_cast<__half2*>(g_Fhi);
        __half2* Flo2 = reinterpret_cast<__half2*>(g_Flo);
        int o_s = (k * 1024 + i2) >> 1;
        int o_c = ((NK + k) * 1024 + i2) >> 1;
        Fhi2[o_s] = __halves2half2(sh0, sh1);
        Fhi2[o_c] = __halves2half2(ch0, ch1);
        Flo2[o_s] = __halves2half2(__float2half_rn(s0 - __half2float(sh0)),
                                   __float2half_rn(s1 - __half2float(sh1)));
        Flo2[o_c] = __halves2half2(__float2half_rn(c0 - __half2float(ch0)),
                                   __float2half_rn(c1 - __half2float(ch1)));
        return;
    }
    int idx = (b - 704) * 256 + threadIdx.x;
    int kp = idx % 48;
    int j  = idx / 48;
    int k2 = kp << 1;
    float p = (float)(j + 1) / 1025.0f;

    float gs[2], gc[2];
#pragma unroll
    for (int q = 0; q < 2; q++) {
        int k = k2 + q;
        float w1 = omega[3 * k + 1], w2 = omega[3 * k + 2];
        float Bv = fmaf(w1, p, fmaf(w2, 0.5f, phi[k]));
        float sb, cb;
        sincosf(Bv, &sb, &cb);
        float as = alpha[k], ac = alpha[NK + k];
        gs[q] = (as * cb - ac * sb) * G_SCALE;
        gc[q] = (as * sb + ac * cb) * G_SCALE;
    }
    h16 gsh0 = __float2half_rn(gs[0]), gsh1 = __float2half_rn(gs[1]);
    h16 gch0 = __float2half_rn(gc[0]), gch1 = __float2half_rn(gc[1]);
    __half2* Ghi2 = reinterpret_cast<__half2*>(g_Ghi);
    __half2* Glo2 = reinterpret_cast<__half2*>(g_Glo);
    int o_s = (j * RANK + k2) >> 1;
    int o_c = (j * RANK + NK + k2) >> 1;
    Ghi2[o_s] = __halves2half2(gsh0, gsh1);
    Ghi2[o_c] = __halves2half2(gch0, gch1);
    Glo2[o_s] = __halves2half2(__float2half_rn(gs[0] - __half2float(gsh0)),
                               __float2half_rn(gs[1] - __half2float(gsh1)));
    Glo2[o_c] = __halves2half2(__float2half_rn(gc[0] - __half2float(gch0)),
                               __float2half_rn(gc[1] - __half2float(gch1)));
}

// ---------------------------------------------------------------------------
// HMMA NT GEMM, fp16, B-side error compensation:
//   C = A @ Bhi^T + A @ Blo^T   (fp32 accum, A fragments shared by both passes)
// Ring pipeline, one sync per 32-K chunk. MINB CTAs/SM target.
// MODE 0: write fp16 C (Ch).  MODE 1: write fp32 SCALE_EPI*acc + bias.
// ---------------------------------------------------------------------------
template <int BM, int BN, int NT, int WARPS_M, int WARPS_N, int STAGES, int NC, int MODE,
          int MINB>
__global__ __launch_bounds__(NT, MINB) void gemm_mma_kernel(
    const h16* __restrict__ A, int KA,
    const h16* __restrict__ Bhi, const h16* __restrict__ Blo,
    float* __restrict__ Cf, h16* __restrict__ Ch,
    int N_total, const float* __restrict__ bias) {
    constexpr int STR = 40;                       // 32 + 8 pad (halves)
    constexpr int WM = BM / WARPS_M;              // 32
    constexpr int WN = BN / WARPS_N;              // 32
    constexpr int MI = WM / 16;                   // 2
    constexpr int NJ = WN / 16;                   // 2
    constexpr int ROWS = BM + 2 * BN;
    constexpr int SS = ROWS * STR;                // halves per stage
    constexpr int LD_ITERS = ROWS * 4 / NT;

    extern __shared__ h16 smem[];
    const uint32_t su = smem_u32(smem);

    const int t = threadIdx.x, w = t >> 5, lane = t & 31;
    const int wm = w % WARPS_M, wn = w / WARPS_M;
    const int m0 = blockIdx.y * BM, n0 = blockIdx.x * BN;

    auto issue = [&](int c, int buf) {
        const int k0 = c * 32;
        const uint32_t sbase = su + buf * SS * 2;
#pragma unroll
        for (int i = 0; i < LD_ITERS; i++) {
            int idx = t + i * NT;
            int r = idx >> 2, c8 = (idx & 3) * 8;
            const h16* g;
            uint32_t soff;
            if (r < BM)           { g = A   + (size_t)(m0 + r) * KA + k0 + c8;            soff = r * STR + c8; }
            else if (r < BM + BN) { int rr = r - BM;      g = Bhi + (size_t)(n0 + rr) * KA + k0 + c8; soff = (BM + rr) * STR + c8; }
            else                  { int rr = r - BM - BN; g = Blo + (size_t)(n0 + rr) * KA + k0 + c8; soff = (BM + BN + rr) * STR + c8; }
            cp_async16(sbase + soff * 2, g);
        }
        cp_commit();
    };

    float acc[MI][2 * NJ][4];
#pragma unroll
    for (int mi = 0; mi < MI; mi++)
#pragma unroll
        for (int ni = 0; ni < 2 * NJ; ni++)
#pragma unroll
            for (int q = 0; q < 4; q++) acc[mi][ni][q] = 0.0f;

    auto compute = [&](int buf) {
        const uint32_t sbase = su + buf * SS * 2;
        uint32_t aF[2][MI][4], bH[2][NJ][4], bL[2][NJ][4];
#pragma unroll
        for (int kk = 0; kk < 2; kk++)
#pragma unroll
            for (int mi = 0; mi < MI; mi++) {
                uint32_t addr = sbase +
                    ((wm * WM + mi * 16 + (lane & 15)) * STR + kk * 16 + (lane >> 4) * 8) * 2;
                ldm_x4(aF[kk][mi][0], aF[kk][mi][1], aF[kk][mi][2], aF[kk][mi][3], addr);
            }
#pragma unroll
        for (int kk = 0; kk < 2; kk++)
#pragma unroll
            for (int nj = 0; nj < NJ; nj++) {
                uint32_t addr = sbase + (BM * STR) * 2 +
                    ((wn * WN + nj * 16 + (lane & 15)) * STR + kk * 16 + (lane >> 4) * 8) * 2;
                ldm_x4(bH[kk][nj][0], bH[kk][nj][1], bH[kk][nj][2], bH[kk][nj][3], addr);
                ldm_x4(bL[kk][nj][0], bL[kk][nj][1], bL[kk][nj][2], bL[kk][nj][3],
                       addr + BN * STR * 2);
            }
#pragma unroll
        for (int kk = 0; kk < 2; kk++)
#pragma unroll
            for (int mi = 0; mi < MI; mi++)
#pragma unroll
                for (int nj = 0; nj < NJ; nj++) {
                    mma_fp16(acc[mi][2 * nj],     aF[kk][mi], bH[kk][nj][0], bH[kk][nj][2]);
                    mma_fp16(acc[mi][2 * nj + 1], aF[kk][mi], bH[kk][nj][1], bH[kk][nj][3]);
                    mma_fp16(acc[mi][2 * nj],     aF[kk][mi], bL[kk][nj][0], bL[kk][nj][2]);
                    mma_fp16(acc[mi][2 * nj + 1], aF[kk][mi], bL[kk][nj][1], bL[kk][nj][3]);
                }
    };

#pragma unroll 1
    for (int s = 0; s < STAGES - 1; s++) issue(s, s);
#pragma unroll 1
    for (int c = 0; c < NC; c++) {
        cp_wait<STAGES - 2>();
        __syncthreads();
        if (c + STAGES - 1 < NC) issue(c + STAGES - 1, (c + STAGES - 1) % STAGES);
        else cp_commit();
        compute(c % STAGES);
    }

    // epilogue
#pragma unroll
    for (int mi = 0; mi < MI; mi++) {
        int r0 = m0 + wm * WM + mi * 16 + (lane >> 2);
#pragma unroll
        for (int ni = 0; ni < 2 * NJ; ni++) {
            int cc = n0 + wn * WN + ni * 8 + (lane & 3) * 2;
            float v0 = acc[mi][ni][0], v1 = acc[mi][ni][1];
            float v2 = acc[mi][ni][2], v3 = acc[mi][ni][3];
            if (MODE == 0) {
                *reinterpret_cast<__half2*>(Ch + (size_t)r0 * N_total + cc) =
                    __floats2half2_rn(v0, v1);
                *reinterpret_cast<__half2*>(Ch + (size_t)(r0 + 8) * N_total + cc) =
                    __floats2half2_rn(v2, v3);
            } else {
                float b0 = bias[cc], b1 = bias[cc + 1];
                float2 o0 = {v0 * SCALE_EPI + b0, v1 * SCALE_EPI + b1};
                float2 o1 = {v2 * SCALE_EPI + b0, v3 * SCALE_EPI + b1};
                *reinterpret_cast<float2*>(Cf + (size_t)r0 * N_total + cc) = o0;
                *reinterpret_cast<float2*>(Cf + (size_t)(r0 + 8) * N_total + cc) = o1;
            }
        }
    }
}

// ---------------------------------------------------------------------------
extern "C" void kernel_launch(void* const* d_in, const int* in_sizes, int n_in,
                              void* d_out, int out_size) {
    const float* x     = (const float*)d_in[0];
    const float* omega = (const float*)d_in[1];
    const float* phi   = (const float*)d_in[2];
    const float* alpha = (const float*)d_in[3];
    const float* bias  = (const float*)d_in[4];
    float* out = (float*)d_out;

    h16 *xh, *Fhi, *Flo, *Ghi, *Glo, *Th;
    cudaGetSymbolAddress((void**)&xh,  g_xh);
    cudaGetSymbolAddress((void**)&Fhi, g_Fhi);
    cudaGetSymbolAddress((void**)&Flo, g_Flo);
    cudaGetSymbolAddress((void**)&Ghi, g_Ghi);
    cudaGetSymbolAddress((void**)&Glo, g_Glo);
    cudaGetSymbolAddress((void**)&Th,  g_Th);

    // GEMM1: BM=64 BN=64, 128 thr, 4-stage ring: smem = 4*192*40*2 = 61440 (3 CTA/SM)
    // GEMM2: BM=128 BN=64, 256 thr, 3-stage ring: smem = 3*256*40*2 = 61440 (3 CTA/SM)
    const int SMEM1 = 4 * (64 + 2 * 64) * 40 * 2;
    const int SMEM2 = 3 * (128 + 2 * 64) * 40 * 2;
    cudaFuncSetAttribute((const void*)gemm_mma_kernel<64, 64, 128, 2, 2, 4, 32, 0, 3>,
                         cudaFuncAttributeMaxDynamicSharedMemorySize, SMEM1);
    cudaFuncSetAttribute((const void*)gemm_mma_kernel<128, 64, 256, 4, 2, 3, 6, 1, 3>,
                         cudaFuncAttributeMaxDynamicSharedMemorySize, SMEM2);

    // prep: [0,512) convert x, [512,704) F, [704,896) G
    prep_kernel<<<896, 256>>>((const float4*)x, omega, phi, alpha);

    // GEMM1: Th = fp16(x @ F^T)   (M=4096, N=192, K=1024), grid 3 x 64 = 192 CTAs
    gemm_mma_kernel<64, 64, 128, 2, 2, 4, 32, 0, 3><<<dim3(RANK / 64, BATCH / 64), 128, SMEM1>>>(
        xh, IN_DIM, Fhi, Flo, nullptr, Th, RANK, nullptr);

    // GEMM2: out = SCALE_EPI*(Th @ G'^T) + bias  (M=4096, N=1024, K=192), grid 16 x 32 = 512
    gemm_mma_kernel<128, 64, 256, 4, 2, 3, 6, 1, 3><<<dim3(OUT_DIM / 64, BATCH / 128), 256, SMEM2>>>(
        Th, RANK, Ghi, Glo, out, nullptr, OUT_DIM, bias);
}

// round 10
// speedup vs baseline: 1.8831x; 1.2192x over previous
#include <cuda_runtime.h>
#include <cuda_fp16.h>
#include <cstdint>
#include <math.h>

#define BATCH   4096
#define IN_DIM  1024
#define OUT_DIM 1024
#define NK      96
#define RANK    192
#define SCALE_F 0.03125f                    // 1/32 exactly
#define G_SCALE 1024.0f                     // keeps Glo in fp16 normal range
#define SCALE_EPI (SCALE_F / G_SCALE)

typedef __half h16;

// ---------------- scratch (device globals) ----------------------------------
__device__ h16 g_xh [BATCH * IN_DIM];
__device__ h16 g_Fhi[RANK * IN_DIM];     // [192][1024] K-major (single, rounded)
__device__ h16 g_Ghi[OUT_DIM * RANK];    // [1024][192] K-major, scaled by 1024
__device__ h16 g_Glo[OUT_DIM * RANK];
__device__ h16 g_Th [BATCH * RANK];

// ---------------- helpers ----------------------------------------------------
__device__ __forceinline__ uint32_t smem_u32(const void* p) {
    uint32_t a;
    asm("{ .reg .u64 t; cvta.to.shared.u64 t, %1; cvt.u32.u64 %0, t; }" : "=r"(a) : "l"(p));
    return a;
}
__device__ __forceinline__ void cp_async16(uint32_t s, const void* g) {
    asm volatile("cp.async.cg.shared.global [%0], [%1], 16;\n" :: "r"(s), "l"(g));
}
__device__ __forceinline__ void cp_commit() {
    asm volatile("cp.async.commit_group;\n" ::: "memory");
}
template <int N>
__device__ __forceinline__ void cp_wait() {
    asm volatile("cp.async.wait_group %0;\n" :: "n"(N) : "memory");
}
__device__ __forceinline__ void ldm_x4(uint32_t& r0, uint32_t& r1, uint32_t& r2, uint32_t& r3,
                                       uint32_t addr) {
    asm volatile("ldmatrix.sync.aligned.m8n8.x4.shared.b16 {%0,%1,%2,%3}, [%4];"
                 : "=r"(r0), "=r"(r1), "=r"(r2), "=r"(r3) : "r"(addr));
}
__device__ __forceinline__ void mma_fp16(float* c, const uint32_t* a, uint32_t b0, uint32_t b1) {
    asm volatile(
        "mma.sync.aligned.m16n8k16.row.col.f32.f16.f16.f32 "
        "{%0,%1,%2,%3}, {%4,%5,%6,%7}, {%8,%9}, {%0,%1,%2,%3};"
        : "+f"(c[0]), "+f"(c[1]), "+f"(c[2]), "+f"(c[3])
        : "r"(a[0]), "r"(a[1]), "r"(a[2]), "r"(a[3]), "r"(b0), "r"(b1));
}
__device__ __forceinline__ uint32_t h2u(__half2 h) { return *reinterpret_cast<uint32_t*>(&h); }

// ---------------------------------------------------------------------------
// prep: blocks [0,512) x->fp16 (MLP=8, 16B stores)
//       blocks [512,704) F factor (single fp16, coalesced half2 stores)
//       blocks [704,896) G factors hi/lo (k-contiguous, coalesced half2 stores)
// ---------------------------------------------------------------------------
__global__ void prep_kernel(const float4* __restrict__ x,
                            const float* __restrict__ omega,
                            const float* __restrict__ phi,
                            const float* __restrict__ alpha) {
    int b = blockIdx.x;
    if (b < 512) {
        int tid = b * 256 + threadIdx.x;
        uint4* dst = reinterpret_cast<uint4*>(g_xh);
        float4 v[8];
#pragma unroll
        for (int p = 0; p < 4; p++) {
            int base = 2 * (tid + p * 131072);
            v[2 * p]     = x[base];
            v[2 * p + 1] = x[base + 1];
        }
#pragma unroll
        for (int p = 0; p < 4; p++) {
            float4 a = v[2 * p], c = v[2 * p + 1];
            uint4 o;
            o.x = h2u(__floats2half2_rn(a.x, a.y));
            o.y = h2u(__floats2half2_rn(a.z, a.w));
            o.z = h2u(__floats2half2_rn(c.x, c.y));
            o.w = h2u(__floats2half2_rn(c.z, c.w));
            dst[tid + p * 131072] = o;
        }
        return;
    }
    if (b < 704) {
        int idx = (b - 512) * 256 + threadIdx.x;
        int i2 = (idx & 511) << 1;
        int k  = idx >> 9;
        float w0 = omega[3 * k + 0];
        float s0, c0, s1, c1;
        sincosf(w0 * ((float)(i2 + 1) / 1025.0f), &s0, &c0);
        sincosf(w0 * ((float)(i2 + 2) / 1025.0f), &s1, &c1);
        __half2* Fhi2 = reinterpret_cast<__half2*>(g_Fhi);
        Fhi2[(k * 1024 + i2) >> 1]        = __floats2half2_rn(s0, s1);
        Fhi2[((NK + k) * 1024 + i2) >> 1] = __floats2half2_rn(c0, c1);
        return;
    }
    int idx = (b - 704) * 256 + threadIdx.x;
    int kp = idx % 48;
    int j  = idx / 48;
    int k2 = kp << 1;
    float p = (float)(j + 1) / 1025.0f;

    float gs[2], gc[2];
#pragma unroll
    for (int q = 0; q < 2; q++) {
        int k = k2 + q;
        float w1 = omega[3 * k + 1], w2 = omega[3 * k + 2];
        float Bv = fmaf(w1, p, fmaf(w2, 0.5f, phi[k]));
        float sb, cb;
        sincosf(Bv, &sb, &cb);
        float as = alpha[k], ac = alpha[NK + k];
        gs[q] = (as * cb - ac * sb) * G_SCALE;
        gc[q] = (as * sb + ac * cb) * G_SCALE;
    }
    h16 gsh0 = __float2half_rn(gs[0]), gsh1 = __float2half_rn(gs[1]);
    h16 gch0 = __float2half_rn(gc[0]), gch1 = __float2half_rn(gc[1]);
    __half2* Ghi2 = reinterpret_cast<__half2*>(g_Ghi);
    __half2* Glo2 = reinterpret_cast<__half2*>(g_Glo);
    int o_s = (j * RANK + k2) >> 1;
    int o_c = (j * RANK + NK + k2) >> 1;
    Ghi2[o_s] = __halves2half2(gsh0, gsh1);
    Ghi2[o_c] = __halves2half2(gch0, gch1);
    Glo2[o_s] = __halves2half2(__float2half_rn(gs[0] - __half2float(gsh0)),
                               __float2half_rn(gs[1] - __half2float(gsh1)));
    Glo2[o_c] = __halves2half2(__float2half_rn(gc[0] - __half2float(gch0)),
                               __float2half_rn(gc[1] - __half2float(gch1)));
}

// ---------------------------------------------------------------------------
// HMMA NT GEMM, fp16. NPASS=1: C = A@Bhi^T. NPASS=2: C = A@Bhi^T + A@Blo^T.
// Ring pipeline, one sync per 32-K chunk.
// MODE 0: write fp16 C (Ch).  MODE 1: write fp32 SCALE_EPI*acc + bias.
// ---------------------------------------------------------------------------
template <int BM, int BN, int NT, int WARPS_M, int WARPS_N, int STAGES, int NC, int MODE,
          int MINB, int NPASS>
__global__ __launch_bounds__(NT, MINB) void gemm_mma_kernel(
    const h16* __restrict__ A, int KA,
    const h16* __restrict__ Bhi, const h16* __restrict__ Blo,
    float* __restrict__ Cf, h16* __restrict__ Ch,
    int N_total, const float* __restrict__ bias) {
    constexpr int STR = 40;                       // 32 + 8 pad (halves)
    constexpr int WM = BM / WARPS_M;              // 32
    constexpr int WN = BN / WARPS_N;              // 32
    constexpr int MI = WM / 16;                   // 2
    constexpr int NJ = WN / 16;                   // 2
    constexpr int ROWS = BM + NPASS * BN;
    constexpr int SS = ROWS * STR;                // halves per stage
    constexpr int LD_ITERS = ROWS * 4 / NT;

    extern __shared__ h16 smem[];
    const uint32_t su = smem_u32(smem);

    const int t = threadIdx.x, w = t >> 5, lane = t & 31;
    const int wm = w % WARPS_M, wn = w / WARPS_M;
    const int m0 = blockIdx.y * BM, n0 = blockIdx.x * BN;

    auto issue = [&](int c, int buf) {
        const int k0 = c * 32;
        const uint32_t sbase = su + buf * SS * 2;
#pragma unroll
        for (int i = 0; i < LD_ITERS; i++) {
            int idx = t + i * NT;
            int r = idx >> 2, c8 = (idx & 3) * 8;
            const h16* g;
            uint32_t soff;
            if (r < BM)           { g = A   + (size_t)(m0 + r) * KA + k0 + c8;            soff = r * STR + c8; }
            else if (r < BM + BN) { int rr = r - BM;      g = Bhi + (size_t)(n0 + rr) * KA + k0 + c8; soff = (BM + rr) * STR + c8; }
            else                  { int rr = r - BM - BN; g = Blo + (size_t)(n0 + rr) * KA + k0 + c8; soff = (BM + BN + rr) * STR + c8; }
            cp_async16(sbase + soff * 2, g);
        }
        cp_commit();
    };

    float acc[MI][2 * NJ][4];
#pragma unroll
    for (int mi = 0; mi < MI; mi++)
#pragma unroll
        for (int ni = 0; ni < 2 * NJ; ni++)
#pragma unroll
            for (int q = 0; q < 4; q++) acc[mi][ni][q] = 0.0f;

    auto compute = [&](int buf) {
        const uint32_t sbase = su + buf * SS * 2;
        uint32_t aF[2][MI][4], bH[2][NJ][4], bL[2][NJ][4];
#pragma unroll
        for (int kk = 0; kk < 2; kk++)
#pragma unroll
            for (int mi = 0; mi < MI; mi++) {
                uint32_t addr = sbase +
                    ((wm * WM + mi * 16 + (lane & 15)) * STR + kk * 16 + (lane >> 4) * 8) * 2;
                ldm_x4(aF[kk][mi][0], aF[kk][mi][1], aF[kk][mi][2], aF[kk][mi][3], addr);
            }
#pragma unroll
        for (int kk = 0; kk < 2; kk++)
#pragma unroll
            for (int nj = 0; nj < NJ; nj++) {
                uint32_t addr = sbase + (BM * STR) * 2 +
                    ((wn * WN + nj * 16 + (lane & 15)) * STR + kk * 16 + (lane >> 4) * 8) * 2;
                ldm_x4(bH[kk][nj][0], bH[kk][nj][1], bH[kk][nj][2], bH[kk][nj][3], addr);
                if (NPASS == 2)
                    ldm_x4(bL[kk][nj][0], bL[kk][nj][1], bL[kk][nj][2], bL[kk][nj][3],
                           addr + BN * STR * 2);
            }
#pragma unroll
        for (int kk = 0; kk < 2; kk++)
#pragma unroll
            for (int mi = 0; mi < MI; mi++)
#pragma unroll
                for (int nj = 0; nj < NJ; nj++) {
                    mma_fp16(acc[mi][2 * nj],     aF[kk][mi], bH[kk][nj][0], bH[kk][nj][2]);
                    mma_fp16(acc[mi][2 * nj + 1], aF[kk][mi], bH[kk][nj][1], bH[kk][nj][3]);
                    if (NPASS == 2) {
                        mma_fp16(acc[mi][2 * nj],     aF[kk][mi], bL[kk][nj][0], bL[kk][nj][2]);
                        mma_fp16(acc[mi][2 * nj + 1], aF[kk][mi], bL[kk][nj][1], bL[kk][nj][3]);
                    }
                }
    };

#pragma unroll 1
    for (int s = 0; s < STAGES - 1; s++) issue(s, s);
#pragma unroll 1
    for (int c = 0; c < NC; c++) {
        cp_wait<STAGES - 2>();
        __syncthreads();
        if (c + STAGES - 1 < NC) issue(c + STAGES - 1, (c + STAGES - 1) % STAGES);
        else cp_commit();
        compute(c % STAGES);
    }

    // epilogue
#pragma unroll
    for (int mi = 0; mi < MI; mi++) {
        int r0 = m0 + wm * WM + mi * 16 + (lane >> 2);
#pragma unroll
        for (int ni = 0; ni < 2 * NJ; ni++) {
            int cc = n0 + wn * WN + ni * 8 + (lane & 3) * 2;
            float v0 = acc[mi][ni][0], v1 = acc[mi][ni][1];
            float v2 = acc[mi][ni][2], v3 = acc[mi][ni][3];
            if (MODE == 0) {
                *reinterpret_cast<__half2*>(Ch + (size_t)r0 * N_total + cc) =
                    __floats2half2_rn(v0, v1);
                *reinterpret_cast<__half2*>(Ch + (size_t)(r0 + 8) * N_total + cc) =
                    __floats2half2_rn(v2, v3);
            } else {
                float b0 = bias[cc], b1 = bias[cc + 1];
                float2 o0 = {v0 * SCALE_EPI + b0, v1 * SCALE_EPI + b1};
                float2 o1 = {v2 * SCALE_EPI + b0, v3 * SCALE_EPI + b1};
                *reinterpret_cast<float2*>(Cf + (size_t)r0 * N_total + cc) = o0;
                *reinterpret_cast<float2*>(Cf + (size_t)(r0 + 8) * N_total + cc) = o1;
            }
        }
    }
}

// ---------------------------------------------------------------------------
extern "C" void kernel_launch(void* const* d_in, const int* in_sizes, int n_in,
                              void* d_out, int out_size) {
    const float* x     = (const float*)d_in[0];
    const float* omega = (const float*)d_in[1];
    const float* phi   = (const float*)d_in[2];
    const float* alpha = (const float*)d_in[3];
    const float* bias  = (const float*)d_in[4];
    float* out = (float*)d_out;

    h16 *xh, *Fhi, *Ghi, *Glo, *Th;
    cudaGetSymbolAddress((void**)&xh,  g_xh);
    cudaGetSymbolAddress((void**)&Fhi, g_Fhi);
    cudaGetSymbolAddress((void**)&Ghi, g_Ghi);
    cudaGetSymbolAddress((void**)&Glo, g_Glo);
    cudaGetSymbolAddress((void**)&Th,  g_Th);

    // GEMM1: BM=64 BN=64 NPASS=1, 128 thr, 6-stage ring: smem = 6*128*40*2 = 61440 (3 CTA/SM)
    // GEMM2: BM=128 BN=64 NPASS=2, 256 thr, 3-stage ring: smem = 3*256*40*2 = 61440 (3 CTA/SM)
    const int SMEM1 = 6 * (64 + 64) * 40 * 2;
    const int SMEM2 = 3 * (128 + 2 * 64) * 40 * 2;
    cudaFuncSetAttribute((const void*)gemm_mma_kernel<64, 64, 128, 2, 2, 6, 32, 0, 3, 1>,
                         cudaFuncAttributeMaxDynamicSharedMemorySize, SMEM1);
    cudaFuncSetAttribute((const void*)gemm_mma_kernel<128, 64, 256, 4, 2, 3, 6, 1, 3, 2>,
                         cudaFuncAttributeMaxDynamicSharedMemorySize, SMEM2);

    // prep: [0,512) convert x, [512,704) F, [704,896) G
    prep_kernel<<<896, 256>>>((const float4*)x, omega, phi, alpha);

    // GEMM1: Th = fp16(x @ F^T)   (M=4096, N=192, K=1024), grid 3 x 64 = 192 CTAs
    gemm_mma_kernel<64, 64, 128, 2, 2, 6, 32, 0, 3, 1><<<dim3(RANK / 64, BATCH / 64), 128, SMEM1>>>(
        xh, IN_DIM, Fhi, nullptr, nullptr, Th, RANK, nullptr);

    // GEMM2: out = SCALE_EPI*(Th @ G'^T) + bias  (M=4096, N=1024, K=192), grid 16 x 32 = 512
    gemm_mma_kernel<128, 64, 256, 4, 2, 3, 6, 1, 3, 2><<<dim3(OUT_DIM / 64, BATCH / 128), 256, SMEM2>>>(
        Th, RANK, Ghi, Glo, out, nullptr, OUT_DIM, bias);
}

// round 11
// speedup vs baseline: 2.0901x; 1.1099x over previous
#include <cuda_runtime.h>
#include <cuda_fp16.h>
#include <cstdint>
#include <math.h>

#define BATCH   4096
#define IN_DIM  1024
#define OUT_DIM 1024
#define NK      96
#define RANK    192
#define SCALE_F 0.03125f                    // 1/32 exactly
#define G_SCALE 1024.0f
#define SCALE_EPI (SCALE_F / G_SCALE)

typedef __half h16;

// ---------------- scratch (device globals) ----------------------------------
__device__ h16 g_xh [BATCH * IN_DIM];
__device__ h16 g_Fhi[RANK * IN_DIM];     // [192][1024] K-major
__device__ h16 g_Ghi[OUT_DIM * RANK];    // [1024][192] K-major, scaled by 1024
__device__ h16 g_Th [BATCH * RANK];

// ---------------- helpers ----------------------------------------------------
__device__ __forceinline__ uint32_t smem_u32(const void* p) {
    uint32_t a;
    asm("{ .reg .u64 t; cvta.to.shared.u64 t, %1; cvt.u32.u64 %0, t; }" : "=r"(a) : "l"(p));
    return a;
}
__device__ __forceinline__ void cp_async16(uint32_t s, const void* g) {
    asm volatile("cp.async.cg.shared.global [%0], [%1], 16;\n" :: "r"(s), "l"(g));
}
__device__ __forceinline__ void cp_commit() {
    asm volatile("cp.async.commit_group;\n" ::: "memory");
}
template <int N>
__device__ __forceinline__ void cp_wait() {
    asm volatile("cp.async.wait_group %0;\n" :: "n"(N) : "memory");
}
__device__ __forceinline__ void ldm_x4(uint32_t& r0, uint32_t& r1, uint32_t& r2, uint32_t& r3,
                                       uint32_t addr) {
    asm volatile("ldmatrix.sync.aligned.m8n8.x4.shared.b16 {%0,%1,%2,%3}, [%4];"
                 : "=r"(r0), "=r"(r1), "=r"(r2), "=r"(r3) : "r"(addr));
}
__device__ __forceinline__ void mma_fp16(float* c, const uint32_t* a, uint32_t b0, uint32_t b1) {
    asm volatile(
        "mma.sync.aligned.m16n8k16.row.col.f32.f16.f16.f32 "
        "{%0,%1,%2,%3}, {%4,%5,%6,%7}, {%8,%9}, {%0,%1,%2,%3};"
        : "+f"(c[0]), "+f"(c[1]), "+f"(c[2]), "+f"(c[3])
        : "r"(a[0]), "r"(a[1]), "r"(a[2]), "r"(a[3]), "r"(b0), "r"(b1));
}
__device__ __forceinline__ uint32_t h2u(__half2 h) { return *reinterpret_cast<uint32_t*>(&h); }

// ---------------------------------------------------------------------------
// prep: blocks [0,512) x->fp16 (MLP=8, 16B stores)
//       blocks [512,704) F factor (fp16, coalesced half2 stores)
//       blocks [704,896) G factor (fp16, scaled, coalesced half2 stores)
// ---------------------------------------------------------------------------
__global__ void prep_kernel(const float4* __restrict__ x,
                            const float* __restrict__ omega,
                            const float* __restrict__ phi,
                            const float* __restrict__ alpha) {
    int b = blockIdx.x;
    if (b < 512) {
        int tid = b * 256 + threadIdx.x;
        uint4* dst = reinterpret_cast<uint4*>(g_xh);
        float4 v[8];
#pragma unroll
        for (int p = 0; p < 4; p++) {
            int base = 2 * (tid + p * 131072);
            v[2 * p]     = x[base];
            v[2 * p + 1] = x[base + 1];
        }
#pragma unroll
        for (int p = 0; p < 4; p++) {
            float4 a = v[2 * p], c = v[2 * p + 1];
            uint4 o;
            o.x = h2u(__floats2half2_rn(a.x, a.y));
            o.y = h2u(__floats2half2_rn(a.z, a.w));
            o.z = h2u(__floats2half2_rn(c.x, c.y));
            o.w = h2u(__floats2half2_rn(c.z, c.w));
            dst[tid + p * 131072] = o;
        }
        return;
    }
    if (b < 704) {
        int idx = (b - 512) * 256 + threadIdx.x;
        int i2 = (idx & 511) << 1;
        int k  = idx >> 9;
        float w0 = omega[3 * k + 0];
        float s0, c0, s1, c1;
        sincosf(w0 * ((float)(i2 + 1) / 1025.0f), &s0, &c0);
        sincosf(w0 * ((float)(i2 + 2) / 1025.0f), &s1, &c1);
        __half2* Fhi2 = reinterpret_cast<__half2*>(g_Fhi);
        Fhi2[(k * 1024 + i2) >> 1]        = __floats2half2_rn(s0, s1);
        Fhi2[((NK + k) * 1024 + i2) >> 1] = __floats2half2_rn(c0, c1);
        return;
    }
    int idx = (b - 704) * 256 + threadIdx.x;
    int kp = idx % 48;
    int j  = idx / 48;
    int k2 = kp << 1;
    float p = (float)(j + 1) / 1025.0f;

    float gs[2], gc[2];
#pragma unroll
    for (int q = 0; q < 2; q++) {
        int k = k2 + q;
        float w1 = omega[3 * k + 1], w2 = omega[3 * k + 2];
        float Bv = fmaf(w1, p, fmaf(w2, 0.5f, phi[k]));
        float sb, cb;
        sincosf(Bv, &sb, &cb);
        float as = alpha[k], ac = alpha[NK + k];
        gs[q] = (as * cb - ac * sb) * G_SCALE;
        gc[q] = (as * sb + ac * cb) * G_SCALE;
    }
    __half2* Ghi2 = reinterpret_cast<__half2*>(g_Ghi);
    Ghi2[(j * RANK + k2) >> 1]      = __floats2half2_rn(gs[0], gs[1]);
    Ghi2[(j * RANK + NK + k2) >> 1] = __floats2half2_rn(gc[0], gc[1]);
}

// ---------------------------------------------------------------------------
// HMMA NT GEMM, fp16, single pass: C = A @ B^T (fp32 accum).
// Ring pipeline, one sync per 32-K chunk.
// MODE 0: write fp16 C (Ch).  MODE 1: write fp32 SCALE_EPI*acc + bias.
// ---------------------------------------------------------------------------
template <int BM, int BN, int NT, int WARPS_M, int WARPS_N, int STAGES, int NC, int MODE,
          int MINB>
__global__ __launch_bounds__(NT, MINB) void gemm_mma_kernel(
    const h16* __restrict__ A, int KA,
    const h16* __restrict__ B,
    float* __restrict__ Cf, h16* __restrict__ Ch,
    int N_total, const float* __restrict__ bias) {
    constexpr int STR = 40;                       // 32 + 8 pad (halves)
    constexpr int WM = BM / WARPS_M;              // 32
    constexpr int WN = BN / WARPS_N;              // 32
    constexpr int MI = WM / 16;                   // 2
    constexpr int NJ = WN / 16;                   // 2
    constexpr int ROWS = BM + BN;
    constexpr int SS = ROWS * STR;                // halves per stage
    constexpr int LD_ITERS = ROWS * 4 / NT;

    extern __shared__ h16 smem[];
    const uint32_t su = smem_u32(smem);

    const int t = threadIdx.x, w = t >> 5, lane = t & 31;
    const int wm = w % WARPS_M, wn = w / WARPS_M;
    const int m0 = blockIdx.y * BM, n0 = blockIdx.x * BN;

    auto issue = [&](int c, int buf) {
        const int k0 = c * 32;
        const uint32_t sbase = su + buf * SS * 2;
#pragma unroll
        for (int i = 0; i < LD_ITERS; i++) {
            int idx = t + i * NT;
            int r = idx >> 2, c8 = (idx & 3) * 8;
            const h16* g;
            uint32_t soff;
            if (r < BM) { g = A + (size_t)(m0 + r) * KA + k0 + c8;                soff = r * STR + c8; }
            else        { int rr = r - BM; g = B + (size_t)(n0 + rr) * KA + k0 + c8; soff = (BM + rr) * STR + c8; }
            cp_async16(sbase + soff * 2, g);
        }
        cp_commit();
    };

    float acc[MI][2 * NJ][4];
#pragma unroll
    for (int mi = 0; mi < MI; mi++)
#pragma unroll
        for (int ni = 0; ni < 2 * NJ; ni++)
#pragma unroll
            for (int q = 0; q < 4; q++) acc[mi][ni][q] = 0.0f;

    auto compute = [&](int buf) {
        const uint32_t sbase = su + buf * SS * 2;
        uint32_t aF[2][MI][4], bF[2][NJ][4];
#pragma unroll
        for (int kk = 0; kk < 2; kk++)
#pragma unroll
            for (int mi = 0; mi < MI; mi++) {
                uint32_t addr = sbase +
                    ((wm * WM + mi * 16 + (lane & 15)) * STR + kk * 16 + (lane >> 4) * 8) * 2;
                ldm_x4(aF[kk][mi][0], aF[kk][mi][1], aF[kk][mi][2], aF[kk][mi][3], addr);
            }
#pragma unroll
        for (int kk = 0; kk < 2; kk++)
#pragma unroll
            for (int nj = 0; nj < NJ; nj++) {
                uint32_t addr = sbase + (BM * STR) * 2 +
                    ((wn * WN + nj * 16 + (lane & 15)) * STR + kk * 16 + (lane >> 4) * 8) * 2;
                ldm_x4(bF[kk][nj][0], bF[kk][nj][1], bF[kk][nj][2], bF[kk][nj][3], addr);
            }
#pragma unroll
        for (int kk = 0; kk < 2; kk++)
#pragma unroll
            for (int mi = 0; mi < MI; mi++)
#pragma unroll
                for (int nj = 0; nj < NJ; nj++) {
                    mma_fp16(acc[mi][2 * nj],     aF[kk][mi], bF[kk][nj][0], bF[kk][nj][2]);
                    mma_fp16(acc[mi][2 * nj + 1], aF[kk][mi], bF[kk][nj][1], bF[kk][nj][3]);
                }
    };

#pragma unroll 1
    for (int s = 0; s < STAGES - 1; s++) issue(s, s);
#pragma unroll 1
    for (int c = 0; c < NC; c++) {
        cp_wait<STAGES - 2>();
        __syncthreads();
        if (c + STAGES - 1 < NC) issue(c + STAGES - 1, (c + STAGES - 1) % STAGES);
        else cp_commit();
        compute(c % STAGES);
    }

    // epilogue
#pragma unroll
    for (int mi = 0; mi < MI; mi++) {
        int r0 = m0 + wm * WM + mi * 16 + (lane >> 2);
#pragma unroll
        for (int ni = 0; ni < 2 * NJ; ni++) {
            int cc = n0 + wn * WN + ni * 8 + (lane & 3) * 2;
            float v0 = acc[mi][ni][0], v1 = acc[mi][ni][1];
            float v2 = acc[mi][ni][2], v3 = acc[mi][ni][3];
            if (MODE == 0) {
                *reinterpret_cast<__half2*>(Ch + (size_t)r0 * N_total + cc) =
                    __floats2half2_rn(v0, v1);
                *reinterpret_cast<__half2*>(Ch + (size_t)(r0 + 8) * N_total + cc) =
                    __floats2half2_rn(v2, v3);
            } else {
                float b0 = bias[cc], b1 = bias[cc + 1];
                float2 o0 = {v0 * SCALE_EPI + b0, v1 * SCALE_EPI + b1};
                float2 o1 = {v2 * SCALE_EPI + b0, v3 * SCALE_EPI + b1};
                *reinterpret_cast<float2*>(Cf + (size_t)r0 * N_total + cc) = o0;
                *reinterpret_cast<float2*>(Cf + (size_t)(r0 + 8) * N_total + cc) = o1;
            }
        }
    }
}

// ---------------------------------------------------------------------------
extern "C" void kernel_launch(void* const* d_in, const int* in_sizes, int n_in,
                              void* d_out, int out_size) {
    const float* x     = (const float*)d_in[0];
    const float* omega = (const float*)d_in[1];
    const float* phi   = (const float*)d_in[2];
    const float* alpha = (const float*)d_in[3];
    const float* bias  = (const float*)d_in[4];
    float* out = (float*)d_out;

    h16 *xh, *Fhi, *Ghi, *Th;
    cudaGetSymbolAddress((void**)&xh,  g_xh);
    cudaGetSymbolAddress((void**)&Fhi, g_Fhi);
    cudaGetSymbolAddress((void**)&Ghi, g_Ghi);
    cudaGetSymbolAddress((void**)&Th,  g_Th);

    // GEMM1: BM=64 BN=64, 128 thr, 6-stage ring: smem = 6*128*40*2 = 61440 (3 CTA/SM)
    // GEMM2: BM=128 BN=64, 256 thr, 4-stage ring: smem = 4*192*40*2 = 61440 (3 CTA/SM)
    const int SMEM1 = 6 * (64 + 64) * 40 * 2;
    const int SMEM2 = 4 * (128 + 64) * 40 * 2;
    cudaFuncSetAttribute((const void*)gemm_mma_kernel<64, 64, 128, 2, 2, 6, 32, 0, 3>,
                         cudaFuncAttributeMaxDynamicSharedMemorySize, SMEM1);
    cudaFuncSetAttribute((const void*)gemm_mma_kernel<128, 64, 256, 4, 2, 4, 6, 1, 3>,
                         cudaFuncAttributeMaxDynamicSharedMemorySize, SMEM2);

    // prep: [0,512) convert x, [512,704) F, [704,896) G
    prep_kernel<<<896, 256>>>((const float4*)x, omega, phi, alpha);

    // GEMM1: Th = fp16(x @ F^T)   (M=4096, N=192, K=1024), grid 3 x 64 = 192 CTAs
    gemm_mma_kernel<64, 64, 128, 2, 2, 6, 32, 0, 3><<<dim3(RANK / 64, BATCH / 64), 128, SMEM1>>>(
        xh, IN_DIM, Fhi, nullptr, Th, RANK, nullptr);

    // GEMM2: out = SCALE_EPI*(Th @ G'^T) + bias  (M=4096, N=1024, K=192), grid 16 x 32 = 512
    gemm_mma_kernel<128, 64, 256, 4, 2, 4, 6, 1, 3><<<dim3(OUT_DIM / 64, BATCH / 128), 256, SMEM2>>>(
        Th, RANK, Ghi, out, nullptr, OUT_DIM, bias);
}

// round 12
// speedup vs baseline: 2.2116x; 1.0582x over previous
#include <cuda_runtime.h>
#include <cuda_fp16.h>
#include <cstdint>
#include <math.h>

#define BATCH   4096
#define IN_DIM  1024
#define OUT_DIM 1024
#define NK      96
#define RANK    192
#define SCALE_F 0.03125f                    // 1/32 exactly
#define G_SCALE 1024.0f
#define SCALE_EPI (SCALE_F / G_SCALE)

typedef __half h16;

// ---------------- scratch (device globals) ----------------------------------
__device__ h16 g_xh [BATCH * IN_DIM];
__device__ h16 g_Fhi[RANK * IN_DIM];     // [192][1024] K-major
__device__ h16 g_Ghi[OUT_DIM * RANK];    // [1024][192] K-major, scaled by 1024
__device__ h16 g_Th [BATCH * RANK];

// ---------------- helpers ----------------------------------------------------
__device__ __forceinline__ uint32_t smem_u32(const void* p) {
    uint32_t a;
    asm("{ .reg .u64 t; cvta.to.shared.u64 t, %1; cvt.u32.u64 %0, t; }" : "=r"(a) : "l"(p));
    return a;
}
__device__ __forceinline__ void cp_async16(uint32_t s, const void* g) {
    asm volatile("cp.async.cg.shared.global [%0], [%1], 16;\n" :: "r"(s), "l"(g));
}
__device__ __forceinline__ void cp_commit() {
    asm volatile("cp.async.commit_group;\n" ::: "memory");
}
template <int N>
__device__ __forceinline__ void cp_wait() {
    asm volatile("cp.async.wait_group %0;\n" :: "n"(N) : "memory");
}
__device__ __forceinline__ void ldm_x4(uint32_t& r0, uint32_t& r1, uint32_t& r2, uint32_t& r3,
                                       uint32_t addr) {
    asm volatile("ldmatrix.sync.aligned.m8n8.x4.shared.b16 {%0,%1,%2,%3}, [%4];"
                 : "=r"(r0), "=r"(r1), "=r"(r2), "=r"(r3) : "r"(addr));
}
__device__ __forceinline__ void mma_fp16(float* c, const uint32_t* a, uint32_t b0, uint32_t b1) {
    asm volatile(
        "mma.sync.aligned.m16n8k16.row.col.f32.f16.f16.f32 "
        "{%0,%1,%2,%3}, {%4,%5,%6,%7}, {%8,%9}, {%0,%1,%2,%3};"
        : "+f"(c[0]), "+f"(c[1]), "+f"(c[2]), "+f"(c[3])
        : "r"(a[0]), "r"(a[1]), "r"(a[2]), "r"(a[3]), "r"(b0), "r"(b1));
}
__device__ __forceinline__ uint32_t h2u(__half2 h) { return *reinterpret_cast<uint32_t*>(&h); }

// ---------------------------------------------------------------------------
// prep: blocks [0,512) x->fp16 (MLP=8, 16B stores)
//       blocks [512,704) F factor (fast sincos, coalesced half2 stores)
//       blocks [704,896) G factor (fast sincos, scaled, coalesced half2 stores)
// ---------------------------------------------------------------------------
__global__ void prep_kernel(const float4* __restrict__ x,
                            const float* __restrict__ omega,
                            const float* __restrict__ phi,
                            const float* __restrict__ alpha) {
    int b = blockIdx.x;
    if (b < 512) {
        int tid = b * 256 + threadIdx.x;
        uint4* dst = reinterpret_cast<uint4*>(g_xh);
        float4 v[8];
#pragma unroll
        for (int p = 0; p < 4; p++) {
            int base = 2 * (tid + p * 131072);
            v[2 * p]     = x[base];
            v[2 * p + 1] = x[base + 1];
        }
#pragma unroll
        for (int p = 0; p < 4; p++) {
            float4 a = v[2 * p], c = v[2 * p + 1];
            uint4 o;
            o.x = h2u(__floats2half2_rn(a.x, a.y));
            o.y = h2u(__floats2half2_rn(a.z, a.w));
            o.z = h2u(__floats2half2_rn(c.x, c.y));
            o.w = h2u(__floats2half2_rn(c.z, c.w));
            dst[tid + p * 131072] = o;
        }
        return;
    }
    if (b < 704) {
        int idx = (b - 512) * 256 + threadIdx.x;
        int i2 = (idx & 511) << 1;
        int k  = idx >> 9;
        float w0 = omega[3 * k + 0];
        float s0, c0, s1, c1;
        __sincosf(w0 * ((float)(i2 + 1) / 1025.0f), &s0, &c0);
        __sincosf(w0 * ((float)(i2 + 2) / 1025.0f), &s1, &c1);
        __half2* Fhi2 = reinterpret_cast<__half2*>(g_Fhi);
        Fhi2[(k * 1024 + i2) >> 1]        = __floats2half2_rn(s0, s1);
        Fhi2[((NK + k) * 1024 + i2) >> 1] = __floats2half2_rn(c0, c1);
        return;
    }
    int idx = (b - 704) * 256 + threadIdx.x;
    int kp = idx % 48;
    int j  = idx / 48;
    int k2 = kp << 1;
    float p = (float)(j + 1) / 1025.0f;

    float gs[2], gc[2];
#pragma unroll
    for (int q = 0; q < 2; q++) {
        int k = k2 + q;
        float w1 = omega[3 * k + 1], w2 = omega[3 * k + 2];
        float Bv = fmaf(w1, p, fmaf(w2, 0.5f, phi[k]));
        float sb, cb;
        __sincosf(Bv, &sb, &cb);
        float as = alpha[k], ac = alpha[NK + k];
        gs[q] = (as * cb - ac * sb) * G_SCALE;
        gc[q] = (as * sb + ac * cb) * G_SCALE;
    }
    __half2* Ghi2 = reinterpret_cast<__half2*>(g_Ghi);
    Ghi2[(j * RANK + k2) >> 1]      = __floats2half2_rn(gs[0], gs[1]);
    Ghi2[(j * RANK + NK + k2) >> 1] = __floats2half2_rn(gc[0], gc[1]);
}

// ---------------------------------------------------------------------------
// GEMM1: Th = fp16(x @ F^T). fp16 single pass, BK=64 per pipeline iteration.
// BM=64, BN=64, 128 thr (2x2 warps), 3-stage ring, 16 iterations.
// ---------------------------------------------------------------------------
__global__ __launch_bounds__(128, 3) void gemm1_kernel(
    const h16* __restrict__ A,
    const h16* __restrict__ B,
    h16* __restrict__ Ch) {
    constexpr int KA = IN_DIM;
    constexpr int STR = 72;                  // 64 + 8 pad (halves)
    constexpr int SS = (64 + 64) * STR;      // halves per stage (9216)
    constexpr int STAGES = 3, NC = 16;

    extern __shared__ h16 smem[];
    const uint32_t su = smem_u32(smem);

    const int t = threadIdx.x, w = t >> 5, lane = t & 31;
    const int wm = w & 1, wn = w >> 1;
    const int m0 = blockIdx.y * 64, n0 = blockIdx.x * 64;

    auto issue = [&](int c, int buf) {
        const int k0 = c * 64;
        const uint32_t sbase = su + buf * SS * 2;
        int r = t >> 3, c8 = (t & 7) * 8;
#pragma unroll
        for (int i = 0; i < 4; i++) {
            int rr = r + i * 16;
            cp_async16(sbase + (rr * STR + c8) * 2, A + (size_t)(m0 + rr) * KA + k0 + c8);
        }
#pragma unroll
        for (int i = 0; i < 4; i++) {
            int rr = r + i * 16;
            cp_async16(sbase + ((64 + rr) * STR + c8) * 2, B + (size_t)(n0 + rr) * KA + k0 + c8);
        }
        cp_commit();
    };

    float acc[2][4][4];
#pragma unroll
    for (int mi = 0; mi < 2; mi++)
#pragma unroll
        for (int ni = 0; ni < 4; ni++)
#pragma unroll
            for (int q = 0; q < 4; q++) acc[mi][ni][q] = 0.0f;

    auto compute = [&](int buf) {
        const uint32_t sbase = su + buf * SS * 2;
        uint32_t aF[4][2][4], bF[4][2][4];
#pragma unroll
        for (int kk = 0; kk < 4; kk++)
#pragma unroll
            for (int mi = 0; mi < 2; mi++) {
                uint32_t addr = sbase +
                    ((wm * 32 + mi * 16 + (lane & 15)) * STR + kk * 16 + (lane >> 4) * 8) * 2;
                ldm_x4(aF[kk][mi][0], aF[kk][mi][1], aF[kk][mi][2], aF[kk][mi][3], addr);
            }
#pragma unroll
        for (int kk = 0; kk < 4; kk++)
#pragma unroll
            for (int nj = 0; nj < 2; nj++) {
                uint32_t addr = sbase + (64 * STR) * 2 +
                    ((wn * 32 + nj * 16 + (lane & 15)) * STR + kk * 16 + (lane >> 4) * 8) * 2;
                ldm_x4(bF[kk][nj][0], bF[kk][nj][1], bF[kk][nj][2], bF[kk][nj][3], addr);
            }
#pragma unroll
        for (int kk = 0; kk < 4; kk++)
#pragma unroll
            for (int mi = 0; mi < 2; mi++)
#pragma unroll
                for (int nj = 0; nj < 2; nj++) {
                    mma_fp16(acc[mi][2 * nj],     aF[kk][mi], bF[kk][nj][0], bF[kk][nj][2]);
                    mma_fp16(acc[mi][2 * nj + 1], aF[kk][mi], bF[kk][nj][1], bF[kk][nj][3]);
                }
    };

#pragma unroll 1
    for (int s = 0; s < STAGES - 1; s++) issue(s, s);
#pragma unroll 1
    for (int c = 0; c < NC; c++) {
        cp_wait<STAGES - 2>();
        __syncthreads();
        if (c + STAGES - 1 < NC) issue(c + STAGES - 1, (c + STAGES - 1) % STAGES);
        else cp_commit();
        compute(c % STAGES);
    }

#pragma unroll
    for (int mi = 0; mi < 2; mi++) {
        int r0 = m0 + wm * 32 + mi * 16 + (lane >> 2);
#pragma unroll
        for (int ni = 0; ni < 4; ni++) {
            int cc = n0 + wn * 32 + ni * 8 + (lane & 3) * 2;
            *reinterpret_cast<__half2*>(Ch + (size_t)r0 * RANK + cc) =
                __floats2half2_rn(acc[mi][ni][0], acc[mi][ni][1]);
            *reinterpret_cast<__half2*>(Ch + (size_t)(r0 + 8) * RANK + cc) =
                __floats2half2_rn(acc[mi][ni][2], acc[mi][ni][3]);
        }
    }
}

// ---------------------------------------------------------------------------
// GEMM2: out = SCALE_EPI*(Th @ G'^T) + bias. fp16 single pass, BK=32.
// BM=128, BN=64, 256 thr (4x2 warps), 4-stage ring, 6 iterations.
// ---------------------------------------------------------------------------
__global__ __launch_bounds__(256, 3) void gemm2_kernel(
    const h16* __restrict__ A,
    const h16* __restrict__ B,
    float* __restrict__ Cf, const float* __restrict__ bias) {
    constexpr int KA = RANK;
    constexpr int STR = 40;                  // 32 + 8 pad
    constexpr int SS = (128 + 64) * STR;     // halves per stage
    constexpr int STAGES = 4, NC = 6;

    extern __shared__ h16 smem[];
    const uint32_t su = smem_u32(smem);

    const int t = threadIdx.x, w = t >> 5, lane = t & 31;
    const int wm = w & 3, wn = w >> 2;
    const int m0 = blockIdx.y * 128, n0 = blockIdx.x * 64;

    auto issue = [&](int c, int buf) {
        const int k0 = c * 32;
        const uint32_t sbase = su + buf * SS * 2;
#pragma unroll
        for (int i = 0; i < 3; i++) {
            int idx = t + i * 256;
            int r = idx >> 2, c8 = (idx & 3) * 8;
            const h16* g;
            uint32_t soff;
            if (r < 128) { g = A + (size_t)(m0 + r) * KA + k0 + c8;                soff = r * STR + c8; }
            else         { int rr = r - 128; g = B + (size_t)(n0 + rr) * KA + k0 + c8; soff = (128 + rr) * STR + c8; }
            cp_async16(sbase + soff * 2, g);
        }
        cp_commit();
    };

    float acc[2][4][4];
#pragma unroll
    for (int mi = 0; mi < 2; mi++)
#pragma unroll
        for (int ni = 0; ni < 4; ni++)
#pragma unroll
            for (int q = 0; q < 4; q++) acc[mi][ni][q] = 0.0f;

    auto compute = [&](int buf) {
        const uint32_t sbase = su + buf * SS * 2;
        uint32_t aF[2][2][4], bF[2][2][4];
#pragma unroll
        for (int kk = 0; kk < 2; kk++)
#pragma unroll
            for (int mi = 0; mi < 2; mi++) {
                uint32_t addr = sbase +
                    ((wm * 32 + mi * 16 + (lane & 15)) * STR + kk * 16 + (lane >> 4) * 8) * 2;
                ldm_x4(aF[kk][mi][0], aF[kk][mi][1], aF[kk][mi][2], aF[kk][mi][3], addr);
            }
#pragma unroll
        for (int kk = 0; kk < 2; kk++)
#pragma unroll
            for (int nj = 0; nj < 2; nj++) {
                uint32_t addr = sbase + (128 * STR) * 2 +
                    ((wn * 32 + nj * 16 + (lane & 15)) * STR + kk * 16 + (lane >> 4) * 8) * 2;
                ldm_x4(bF[kk][nj][0], bF[kk][nj][1], bF[kk][nj][2], bF[kk][nj][3], addr);
            }
#pragma unroll
        for (int kk = 0; kk < 2; kk++)
#pragma unroll
            for (int mi = 0; mi < 2; mi++)
#pragma unroll
                for (int nj = 0; nj < 2; nj++) {
                    mma_fp16(acc[mi][2 * nj],     aF[kk][mi], bF[kk][nj][0], bF[kk][nj][2]);
                    mma_fp16(acc[mi][2 * nj + 1], aF[kk][mi], bF[kk][nj][1], bF[kk][nj][3]);
                }
    };

#pragma unroll 1
    for (int s = 0; s < STAGES - 1; s++) issue(s, s);
#pragma unroll 1
    for (int c = 0; c < NC; c++) {
        cp_wait<STAGES - 2>();
        __syncthreads();
        if (c + STAGES - 1 < NC) issue(c + STAGES - 1, (c + STAGES - 1) % STAGES);
        else cp_commit();
        compute(c % STAGES);
    }

#pragma unroll
    for (int mi = 0; mi < 2; mi++) {
        int r0 = m0 + wm * 32 + mi * 16 + (lane >> 2);
#pragma unroll
        for (int ni = 0; ni < 4; ni++) {
            int cc = n0 + wn * 32 + ni * 8 + (lane & 3) * 2;
            float b0 = bias[cc], b1 = bias[cc + 1];
            float2 o0 = {acc[mi][ni][0] * SCALE_EPI + b0, acc[mi][ni][1] * SCALE_EPI + b1};
            float2 o1 = {acc[mi][ni][2] * SCALE_EPI + b0, acc[mi][ni][3] * SCALE_EPI + b1};
            *reinterpret_cast<float2*>(Cf + (size_t)r0 * OUT_DIM + cc) = o0;
            *reinterpret_cast<float2*>(Cf + (size_t)(r0 + 8) * OUT_DIM + cc) = o1;
        }
    }
}

// ---------------------------------------------------------------------------
extern "C" void kernel_launch(void* const* d_in, const int* in_sizes, int n_in,
                              void* d_out, int out_size) {
    const float* x     = (const float*)d_in[0];
    const float* omega = (const float*)d_in[1];
    const float* phi   = (const float*)d_in[2];
    const float* alpha = (const float*)d_in[3];
    const float* bias  = (const float*)d_in[4];
    float* out = (float*)d_out;

    h16 *xh, *Fhi, *Ghi, *Th;
    cudaGetSymbolAddress((void**)&xh,  g_xh);
    cudaGetSymbolAddress((void**)&Fhi, g_Fhi);
    cudaGetSymbolAddress((void**)&Ghi, g_Ghi);
    cudaGetSymbolAddress((void**)&Th,  g_Th);

    const int SMEM1 = 3 * (64 + 64) * 72 * 2;   // 55296, 3 CTA/SM
    const int SMEM2 = 4 * (128 + 64) * 40 * 2;  // 61440, 3 CTA/SM
    cudaFuncSetAttribute((const void*)gemm1_kernel,
                         cudaFuncAttributeMaxDynamicSharedMemorySize, SMEM1);
    cudaFuncSetAttribute((const void*)gemm2_kernel,
                         cudaFuncAttributeMaxDynamicSharedMemorySize, SMEM2);

    // prep: [0,512) convert x, [512,704) F, [704,896) G
    prep_kernel<<<896, 256>>>((const float4*)x, omega, phi, alpha);

    // GEMM1: Th = fp16(x @ F^T)   (M=4096, N=192, K=1024), grid 3 x 64 = 192 CTAs
    gemm1_kernel<<<dim3(RANK / 64, BATCH / 64), 128, SMEM1>>>(xh, Fhi, Th);

    // GEMM2: out = SCALE_EPI*(Th @ G'^T) + bias  (M=4096, N=1024, K=192), grid 16 x 32 = 512
    gemm2_kernel<<<dim3(OUT_DIM / 64, BATCH / 128), 256, SMEM2>>>(Th, Ghi, out, bias);
}

// round 13
// speedup vs baseline: 2.3746x; 1.0737x over previous
#include <cuda_runtime.h>
#include <cuda_fp16.h>
#include <cstdint>
#include <math.h>

#define BATCH   4096
#define IN_DIM  1024
#define OUT_DIM 1024
#define NK      96
#define RANK    192
#define SCALE_F 0.03125f                    // 1/32 exactly
#define G_SCALE 1024.0f
#define SCALE_EPI (SCALE_F / G_SCALE)

typedef __half h16;

// ---------------- scratch (device globals) ----------------------------------
__device__ h16 g_xh [BATCH * IN_DIM];
__device__ h16 g_Fhi[RANK * IN_DIM];     // [192][1024] K-major
__device__ h16 g_Ghi[OUT_DIM * RANK];    // [1024][192] K-major, scaled by 1024
__device__ h16 g_Th [BATCH * RANK];

// ---------------- helpers ----------------------------------------------------
__device__ __forceinline__ uint32_t smem_u32(const void* p) {
    uint32_t a;
    asm("{ .reg .u64 t; cvta.to.shared.u64 t, %1; cvt.u32.u64 %0, t; }" : "=r"(a) : "l"(p));
    return a;
}
__device__ __forceinline__ void cp_async16(uint32_t s, const void* g) {
    asm volatile("cp.async.cg.shared.global [%0], [%1], 16;\n" :: "r"(s), "l"(g));
}
__device__ __forceinline__ void cp_commit() {
    asm volatile("cp.async.commit_group;\n" ::: "memory");
}
template <int N>
__device__ __forceinline__ void cp_wait() {
    asm volatile("cp.async.wait_group %0;\n" :: "n"(N) : "memory");
}
__device__ __forceinline__ void ldm_x4(uint32_t& r0, uint32_t& r1, uint32_t& r2, uint32_t& r3,
                                       uint32_t addr) {
    asm volatile("ldmatrix.sync.aligned.m8n8.x4.shared.b16 {%0,%1,%2,%3}, [%4];"
                 : "=r"(r0), "=r"(r1), "=r"(r2), "=r"(r3) : "r"(addr));
}
__device__ __forceinline__ void mma_fp16(float* c, const uint32_t* a, uint32_t b0, uint32_t b1) {
    asm volatile(
        "mma.sync.aligned.m16n8k16.row.col.f32.f16.f16.f32 "
        "{%0,%1,%2,%3}, {%4,%5,%6,%7}, {%8,%9}, {%0,%1,%2,%3};"
        : "+f"(c[0]), "+f"(c[1]), "+f"(c[2]), "+f"(c[3])
        : "r"(a[0]), "r"(a[1]), "r"(a[2]), "r"(a[3]), "r"(b0), "r"(b1));
}
__device__ __forceinline__ uint32_t h2u(__half2 h) { return *reinterpret_cast<uint32_t*>(&h); }

// ---------------------------------------------------------------------------
// prep: blocks [0,512) x->fp16 (MLP=8, 16B stores)
//       blocks [512,704) F factor (fast sincos, coalesced half2 stores)
//       blocks [704,896) G factor (fast sincos, scaled, coalesced half2 stores)
// ---------------------------------------------------------------------------
__global__ void prep_kernel(const float4* __restrict__ x,
                            const float* __restrict__ omega,
                            const float* __restrict__ phi,
                            const float* __restrict__ alpha) {
    int b = blockIdx.x;
    if (b < 512) {
        int tid = b * 256 + threadIdx.x;
        uint4* dst = reinterpret_cast<uint4*>(g_xh);
        float4 v[8];
#pragma unroll
        for (int p = 0; p < 4; p++) {
            int base = 2 * (tid + p * 131072);
            v[2 * p]     = x[base];
            v[2 * p + 1] = x[base + 1];
        }
#pragma unroll
        for (int p = 0; p < 4; p++) {
            float4 a = v[2 * p], c = v[2 * p + 1];
            uint4 o;
            o.x = h2u(__floats2half2_rn(a.x, a.y));
            o.y = h2u(__floats2half2_rn(a.z, a.w));
            o.z = h2u(__floats2half2_rn(c.x, c.y));
            o.w = h2u(__floats2half2_rn(c.z, c.w));
            dst[tid + p * 131072] = o;
        }
        return;
    }
    if (b < 704) {
        int idx = (b - 512) * 256 + threadIdx.x;
        int i2 = (idx & 511) << 1;
        int k  = idx >> 9;
        float w0 = omega[3 * k + 0];
        float s0, c0, s1, c1;
        __sincosf(w0 * ((float)(i2 + 1) / 1025.0f), &s0, &c0);
        __sincosf(w0 * ((float)(i2 + 2) / 1025.0f), &s1, &c1);
        __half2* Fhi2 = reinterpret_cast<__half2*>(g_Fhi);
        Fhi2[(k * 1024 + i2) >> 1]        = __floats2half2_rn(s0, s1);
        Fhi2[((NK + k) * 1024 + i2) >> 1] = __floats2half2_rn(c0, c1);
        return;
    }
    int idx = (b - 704) * 256 + threadIdx.x;
    int kp = idx % 48;
    int j  = idx / 48;
    int k2 = kp << 1;
    float p = (float)(j + 1) / 1025.0f;

    float gs[2], gc[2];
#pragma unroll
    for (int q = 0; q < 2; q++) {
        int k = k2 + q;
        float w1 = omega[3 * k + 1], w2 = omega[3 * k + 2];
        float Bv = fmaf(w1, p, fmaf(w2, 0.5f, phi[k]));
        float sb, cb;
        __sincosf(Bv, &sb, &cb);
        float as = alpha[k], ac = alpha[NK + k];
        gs[q] = (as * cb - ac * sb) * G_SCALE;
        gc[q] = (as * sb + ac * cb) * G_SCALE;
    }
    __half2* Ghi2 = reinterpret_cast<__half2*>(g_Ghi);
    Ghi2[(j * RANK + k2) >> 1]      = __floats2half2_rn(gs[0], gs[1]);
    Ghi2[(j * RANK + NK + k2) >> 1] = __floats2half2_rn(gc[0], gc[1]);
}

// ---------------------------------------------------------------------------
// GEMM1: Th = fp16(x @ F^T). fp16 single pass, BK=64 per pipeline iteration.
// BM=64, BN=64, 256 thr (4x2 warps, warp tile 16x32), 3-stage ring, 16 iters.
// ---------------------------------------------------------------------------
__global__ __launch_bounds__(256, 2) void gemm1_kernel(
    const h16* __restrict__ A,
    const h16* __restrict__ B,
    h16* __restrict__ Ch) {
    constexpr int KA = IN_DIM;
    constexpr int STR = 72;                  // 64 + 8 pad (halves)
    constexpr int SS = (64 + 64) * STR;      // halves per stage (9216)
    constexpr int STAGES = 3, NC = 16;

    extern __shared__ h16 smem[];
    const uint32_t su = smem_u32(smem);

    const int t = threadIdx.x, w = t >> 5, lane = t & 31;
    const int wm = w & 3, wn = w >> 2;       // 4 warps in M (16 rows each), 2 in N (32 cols)
    const int m0 = blockIdx.y * 64, n0 = blockIdx.x * 64;

    auto issue = [&](int c, int buf) {
        const int k0 = c * 64;
        const uint32_t sbase = su + buf * SS * 2;
        int r = t >> 3, c8 = (t & 7) * 8;    // 32 rows per iteration
#pragma unroll
        for (int i = 0; i < 2; i++) {
            int rr = r + i * 32;
            cp_async16(sbase + (rr * STR + c8) * 2, A + (size_t)(m0 + rr) * KA + k0 + c8);
        }
#pragma unroll
        for (int i = 0; i < 2; i++) {
            int rr = r + i * 32;
            cp_async16(sbase + ((64 + rr) * STR + c8) * 2, B + (size_t)(n0 + rr) * KA + k0 + c8);
        }
        cp_commit();
    };

    float acc[4][4];                          // mi=1, 4 n8-accumulators
#pragma unroll
    for (int ni = 0; ni < 4; ni++)
#pragma unroll
        for (int q = 0; q < 4; q++) acc[ni][q] = 0.0f;

    auto compute = [&](int buf) {
        const uint32_t sbase = su + buf * SS * 2;
        uint32_t aF[4][4], bF[4][2][4];
#pragma unroll
        for (int kk = 0; kk < 4; kk++) {
            uint32_t addr = sbase +
                ((wm * 16 + (lane & 15)) * STR + kk * 16 + (lane >> 4) * 8) * 2;
            ldm_x4(aF[kk][0], aF[kk][1], aF[kk][2], aF[kk][3], addr);
        }
#pragma unroll
        for (int kk = 0; kk < 4; kk++)
#pragma unroll
            for (int nj = 0; nj < 2; nj++) {
                uint32_t addr = sbase + (64 * STR) * 2 +
                    ((wn * 32 + nj * 16 + (lane & 15)) * STR + kk * 16 + (lane >> 4) * 8) * 2;
                ldm_x4(bF[kk][nj][0], bF[kk][nj][1], bF[kk][nj][2], bF[kk][nj][3], addr);
            }
#pragma unroll
        for (int kk = 0; kk < 4; kk++)
#pragma unroll
            for (int nj = 0; nj < 2; nj++) {
                mma_fp16(acc[2 * nj],     aF[kk], bF[kk][nj][0], bF[kk][nj][2]);
                mma_fp16(acc[2 * nj + 1], aF[kk], bF[kk][nj][1], bF[kk][nj][3]);
            }
    };

#pragma unroll 1
    for (int s = 0; s < STAGES - 1; s++) issue(s, s);
#pragma unroll 1
    for (int c = 0; c < NC; c++) {
        cp_wait<STAGES - 2>();
        __syncthreads();
        if (c + STAGES - 1 < NC) issue(c + STAGES - 1, (c + STAGES - 1) % STAGES);
        else cp_commit();
        compute(c % STAGES);
    }

    {
        int r0 = m0 + wm * 16 + (lane >> 2);
#pragma unroll
        for (int ni = 0; ni < 4; ni++) {
            int cc = n0 + wn * 32 + ni * 8 + (lane & 3) * 2;
            *reinterpret_cast<__half2*>(Ch + (size_t)r0 * RANK + cc) =
                __floats2half2_rn(acc[ni][0], acc[ni][1]);
            *reinterpret_cast<__half2*>(Ch + (size_t)(r0 + 8) * RANK + cc) =
                __floats2half2_rn(acc[ni][2], acc[ni][3]);
        }
    }
}

// ---------------------------------------------------------------------------
// GEMM2: out = SCALE_EPI*(Th @ G'^T) + bias. fp16 single pass, BK=32.
// BM=128, BN=64, 256 thr (4x2 warps), 4-stage ring, 6 iterations.
// ---------------------------------------------------------------------------
__global__ __launch_bounds__(256, 3) void gemm2_kernel(
    const h16* __restrict__ A,
    const h16* __restrict__ B,
    float* __restrict__ Cf, const float* __restrict__ bias) {
    constexpr int KA = RANK;
    constexpr int STR = 40;                  // 32 + 8 pad
    constexpr int SS = (128 + 64) * STR;     // halves per stage
    constexpr int STAGES = 4, NC = 6;

    extern __shared__ h16 smem[];
    const uint32_t su = smem_u32(smem);

    const int t = threadIdx.x, w = t >> 5, lane = t & 31;
    const int wm = w & 3, wn = w >> 2;
    const int m0 = blockIdx.y * 128, n0 = blockIdx.x * 64;

    auto issue = [&](int c, int buf) {
        const int k0 = c * 32;
        const uint32_t sbase = su + buf * SS * 2;
#pragma unroll
        for (int i = 0; i < 3; i++) {
            int idx = t + i * 256;
            int r = idx >> 2, c8 = (idx & 3) * 8;
            const h16* g;
            uint32_t soff;
            if (r < 128) { g = A + (size_t)(m0 + r) * KA + k0 + c8;                soff = r * STR + c8; }
            else         { int rr = r - 128; g = B + (size_t)(n0 + rr) * KA + k0 + c8; soff = (128 + rr) * STR + c8; }
            cp_async16(sbase + soff * 2, g);
        }
        cp_commit();
    };

    float acc[2][4][4];
#pragma unroll
    for (int mi = 0; mi < 2; mi++)
#pragma unroll
        for (int ni = 0; ni < 4; ni++)
#pragma unroll
            for (int q = 0; q < 4; q++) acc[mi][ni][q] = 0.0f;

    auto compute = [&](int buf) {
        const uint32_t sbase = su + buf * SS * 2;
        uint32_t aF[2][2][4], bF[2][2][4];
#pragma unroll
        for (int kk = 0; kk < 2; kk++)
#pragma unroll
            for (int mi = 0; mi < 2; mi++) {
                uint32_t addr = sbase +
                    ((wm * 32 + mi * 16 + (lane & 15)) * STR + kk * 16 + (lane >> 4) * 8) * 2;
                ldm_x4(aF[kk][mi][0], aF[kk][mi][1], aF[kk][mi][2], aF[kk][mi][3], addr);
            }
#pragma unroll
        for (int kk = 0; kk < 2; kk++)
#pragma unroll
            for (int nj = 0; nj < 2; nj++) {
                uint32_t addr = sbase + (128 * STR) * 2 +
                    ((wn * 32 + nj * 16 + (lane & 15)) * STR + kk * 16 + (lane >> 4) * 8) * 2;
                ldm_x4(bF[kk][nj][0], bF[kk][nj][1], bF[kk][nj][2], bF[kk][nj][3], addr);
            }
#pragma unroll
        for (int kk = 0; kk < 2; kk++)
#pragma unroll
            for (int mi = 0; mi < 2; mi++)
#pragma unroll
                for (int nj = 0; nj < 2; nj++) {
                    mma_fp16(acc[mi][2 * nj],     aF[kk][mi], bF[kk][nj][0], bF[kk][nj][2]);
                    mma_fp16(acc[mi][2 * nj + 1], aF[kk][mi], bF[kk][nj][1], bF[kk][nj][3]);
                }
    };

#pragma unroll 1
    for (int s = 0; s < STAGES - 1; s++) issue(s, s);
#pragma unroll 1
    for (int c = 0; c < NC; c++) {
        cp_wait<STAGES - 2>();
        __syncthreads();
        if (c + STAGES - 1 < NC) issue(c + STAGES - 1, (c + STAGES - 1) % STAGES);
        else cp_commit();
        compute(c % STAGES);
    }

#pragma unroll
    for (int mi = 0; mi < 2; mi++) {
        int r0 = m0 + wm * 32 + mi * 16 + (lane >> 2);
#pragma unroll
        for (int ni = 0; ni < 4; ni++) {
            int cc = n0 + wn * 32 + ni * 8 + (lane & 3) * 2;
            float b0 = bias[cc], b1 = bias[cc + 1];
            float2 o0 = {acc[mi][ni][0] * SCALE_EPI + b0, acc[mi][ni][1] * SCALE_EPI + b1};
            float2 o1 = {acc[mi][ni][2] * SCALE_EPI + b0, acc[mi][ni][3] * SCALE_EPI + b1};
            *reinterpret_cast<float2*>(Cf + (size_t)r0 * OUT_DIM + cc) = o0;
            *reinterpret_cast<float2*>(Cf + (size_t)(r0 + 8) * OUT_DIM + cc) = o1;
        }
    }
}

// ---------------------------------------------------------------------------
extern "C" void kernel_launch(void* const* d_in, const int* in_sizes, int n_in,
                              void* d_out, int out_size) {
    const float* x     = (const float*)d_in[0];
    const float* omega = (const float*)d_in[1];
    const float* phi   = (const float*)d_in[2];
    const float* alpha = (const float*)d_in[3];
    const float* bias  = (const float*)d_in[4];
    float* out = (float*)d_out;

    h16 *xh, *Fhi, *Ghi, *Th;
    cudaGetSymbolAddress((void**)&xh,  g_xh);
    cudaGetSymbolAddress((void**)&Fhi, g_Fhi);
    cudaGetSymbolAddress((void**)&Ghi, g_Ghi);
    cudaGetSymbolAddress((void**)&Th,  g_Th);

    const int SMEM1 = 3 * (64 + 64) * 72 * 2;   // 55296
    const int SMEM2 = 4 * (128 + 64) * 40 * 2;  // 61440
    cudaFuncSetAttribute((const void*)gemm1_kernel,
                         cudaFuncAttributeMaxDynamicSharedMemorySize, SMEM1);
    cudaFuncSetAttribute((const void*)gemm2_kernel,
                         cudaFuncAttributeMaxDynamicSharedMemorySize, SMEM2);

    // prep: [0,512) convert x, [512,704) F, [704,896) G
    prep_kernel<<<896, 256>>>((const float4*)x, omega, phi, alpha);

    // GEMM1: Th = fp16(x @ F^T)   (M=4096, N=192, K=1024), grid 3 x 64 = 192 CTAs
    gemm1_kernel<<<dim3(RANK / 64, BATCH / 64), 256, SMEM1>>>(xh, Fhi, Th);

    // GEMM2: out = SCALE_EPI*(Th @ G'^T) + bias  (M=4096, N=1024, K=192), grid 16 x 32 = 512
    gemm2_kernel<<<dim3(OUT_DIM / 64, BATCH / 128), 256, SMEM2>>>(Th, Ghi, out, bias);
}